// round 13
// baseline (speedup 1.0000x reference)
#include <cuda_runtime.h>
#include <cuda_bf16.h>
#include <cuda_fp16.h>
#include <math.h>
#include <stdint.h>
#include <cstdint>

// ---------------- Problem constants ----------------
#define DD 256
#define FIN 128
#define CC 7

typedef __half f16;

// ---------------- Scratch layout (float offsets) ----------------
#define OFF_H     0L             // fp32 [M,512]
#define OFF_HF    51200000L      // fp32 [M,256]
#define OFF_XF    76800000L      // f16 [M,512] activations
#define OFF_YF    102400000L     // f16 [M,256]
#define OFF_WH    153600000L     // f16 weight arena hi (720896)
#define OFF_WL    154000000L     // f16 weight arena lo
#define OFF_HID2  154400000L
#define OFF_DIS1  155680000L
#define OFF_DIS2  155780000L
// ---- zero block start ----
#define OFF_CC    155880000L     // int[2N]
#define OFF_SC    156080000L     // int[2S]
#define OFF_BSN   156090000L     // int[256]
#define OFF_BSS   156090256L     // int[16]
// ---- zero block end ----
#define OFF_COFF  156090272L     // int[2N+1]
#define OFF_CCUR  156290276L
#define OFF_SOFF  156490276L     // int[2S+1]
#define OFF_SCUR  156500280L
#define OFF_CSR   156510280L     // int[E1+E2]
#define OFF_SLIST 158110280L     // int[2N]
#define SCRATCH_TOTAL 158310280L

// weight arena offsets (f16 elements)
#define WC1  0
#define WC2  65536
#define WM1A 196608
#define WM1B 327680
#define WM2A 393216
#define WM2B 524288
#define WHD  589824
#define WTOT 720896

__device__ float g_buf[SCRATCH_TOTAL];

// ---------------- helpers ----------------
__device__ __forceinline__ void splithf(float v, f16& h, f16& l) {
    h = __float2half_rn(v);
    l = __float2half_rn(v - __half2float(h));
}

__device__ __forceinline__ void ldm_x4(uint32_t r[4], const void* p) {
    uint32_t addr = (uint32_t)__cvta_generic_to_shared(p);
    asm volatile("ldmatrix.sync.aligned.m8n8.x4.shared.b16 {%0,%1,%2,%3}, [%4];"
                 : "=r"(r[0]), "=r"(r[1]), "=r"(r[2]), "=r"(r[3]) : "r"(addr));
}

__device__ __forceinline__ void mma16816(float c[4], const uint32_t a[4],
                                         uint32_t b0, uint32_t b1) {
    asm volatile(
        "mma.sync.aligned.m16n8k16.row.col.f32.f16.f16.f32 "
        "{%0,%1,%2,%3}, {%4,%5,%6,%7}, {%8,%9}, {%0,%1,%2,%3};"
        : "+f"(c[0]), "+f"(c[1]), "+f"(c[2]), "+f"(c[3])
        : "r"(a[0]), "r"(a[1]), "r"(a[2]), "r"(a[3]), "r"(b0), "r"(b1));
}

__device__ __forceinline__ void cp16(uint32_t s, const void* g, int sz) {
    asm volatile("cp.async.cg.shared.global [%0], [%1], 16, %2;"
                 :: "r"(s), "l"(g), "r"(sz));
}

// ---------------- prologue kernels ----------------
#define SCAN_B 1024

__global__ void zero_k(float* __restrict__ p, int n) {
    int i = blockIdx.x * blockDim.x + threadIdx.x;
    if (i < n) p[i] = 0.0f;
}

__global__ void countall_k(const int* __restrict__ e1, int E1,
                           const int* __restrict__ e2, int E2,
                           const int* __restrict__ i1, const int* __restrict__ i2,
                           int Nn, int S,
                           int* __restrict__ cc, int* __restrict__ sc) {
    int i = blockIdx.x * blockDim.x + threadIdx.x;
    if (i < E1) atomicAdd(&cc[e1[E1 + i]], 1);
    else if (i < E1 + E2) atomicAdd(&cc[Nn + e2[E2 + (i - E1)]], 1);
    else {
        int j = i - E1 - E2;
        if (j < Nn) {
            atomicAdd(&sc[i1[j]], 1);
            atomicAdd(&sc[S + i2[j]], 1);
        }
    }
}

__global__ void blocksum_k(const int* __restrict__ cnt, int* __restrict__ bsum, int n) {
    int i = blockIdx.x * SCAN_B + threadIdx.x;
    int v = (i < n) ? cnt[i] : 0;
    #pragma unroll
    for (int o = 16; o > 0; o >>= 1) v += __shfl_xor_sync(0xFFFFFFFFu, v, o);
    if ((threadIdx.x & 31) == 0) atomicAdd(&bsum[blockIdx.x], v);
}

__global__ void scanbsum_k(int* __restrict__ bsum, int nb, int* __restrict__ off_n) {
    if (threadIdx.x == 0) {
        int acc = 0;
        for (int i = 0; i < nb; i++) { int v = bsum[i]; bsum[i] = acc; acc += v; }
        *off_n = acc;
    }
}

__global__ void scanblock_k(const int* __restrict__ cnt, const int* __restrict__ bsum,
                            int* __restrict__ off, int* __restrict__ cur, int n) {
    __shared__ int sw[32];
    int tid = threadIdx.x, lane = tid & 31, wid = tid >> 5;
    int i = blockIdx.x * SCAN_B + tid;
    int v = (i < n) ? cnt[i] : 0;
    int inc = v;
    #pragma unroll
    for (int o = 1; o < 32; o <<= 1) {
        int t = __shfl_up_sync(0xFFFFFFFFu, inc, o);
        if (lane >= o) inc += t;
    }
    if (lane == 31) sw[wid] = inc;
    __syncthreads();
    if (wid == 0) {
        int t = sw[lane];
        int ti = t;
        #pragma unroll
        for (int o = 1; o < 32; o <<= 1) {
            int u = __shfl_up_sync(0xFFFFFFFFu, ti, o);
            if (lane >= o) ti += u;
        }
        sw[lane] = ti - t;
    }
    __syncthreads();
    int excl = inc - v + sw[wid] + bsum[blockIdx.x];
    if (i < n) { off[i] = excl; cur[i] = excl; }
}

__global__ void disint_k(const int* __restrict__ cc,
                         float* __restrict__ d1, float* __restrict__ d2, int Nn) {
    int i = blockIdx.x * blockDim.x + threadIdx.x;
    if (i < Nn) {
        d1[i] = rsqrtf((float)cc[i] + 1.0f);
        d2[i] = rsqrtf((float)cc[Nn + i] + 1.0f);
    }
}

__global__ void placeboth_k(const int* __restrict__ e1, int E1,
                            const int* __restrict__ e2, int E2, int Nn,
                            int* __restrict__ cur, int* __restrict__ csr) {
    int i = blockIdx.x * blockDim.x + threadIdx.x;
    if (i < E1) {
        int pos = atomicAdd(&cur[e1[E1 + i]], 1);
        csr[pos] = e1[i];
    } else if (i < E1 + E2) {
        int j = i - E1;
        int pos = atomicAdd(&cur[Nn + e2[E2 + j]], 1);
        csr[pos] = e2[j];
    }
}

__global__ void placeseg_k(const int* __restrict__ i1, const int* __restrict__ i2,
                           int Nn, int S,
                           int* __restrict__ scur, int* __restrict__ slist) {
    int i = blockIdx.x * blockDim.x + threadIdx.x;
    if (i < Nn) {
        int p1 = atomicAdd(&scur[i1[i]], 1);
        slist[p1] = i;
        int p2 = atomicAdd(&scur[S + i2[i]], 1);
        slist[p2] = i;
    }
}

// ---------------- gather conv (column-blocked for L2 residency) ----------------
// X[node, ocoff+cblk+c] = f16(relu(bias + d^2 h_i + sum coef h_j))
__global__ void gather_k(const int* __restrict__ csr, const int* __restrict__ off,
                         const float* __restrict__ dis,
                         const float* __restrict__ h,      // pre-offset, stride 512
                         const float* __restrict__ bias,
                         f16* __restrict__ oF,
                         int ocoff, int cblk, int Nn) {
    int node = blockIdx.x * 8 + (threadIdx.x >> 5);
    if (node >= Nn) return;
    int c = cblk + ((threadIdx.x & 31) << 2);
    float di = dis[node];
    float d2 = di * di;
    float4 hv = *(const float4*)(h + (size_t)node * 512 + c);
    float4 bv = *(const float4*)(bias + c);
    float4 acc;
    acc.x = bv.x + d2 * hv.x; acc.y = bv.y + d2 * hv.y;
    acc.z = bv.z + d2 * hv.z; acc.w = bv.w + d2 * hv.w;
    int s = off[node], e = off[node + 1];
    for (int k = s; k < e; k++) {
        int j = csr[k];
        float coef = di * dis[j];
        float4 hj = *(const float4*)(h + (size_t)j * 512 + c);
        acc.x += coef * hj.x; acc.y += coef * hj.y;
        acc.z += coef * hj.z; acc.w += coef * hj.w;
    }
    acc.x = fmaxf(acc.x, 0.f); acc.y = fmaxf(acc.y, 0.f);
    acc.z = fmaxf(acc.z, 0.f); acc.w = fmaxf(acc.w, 0.f);
    size_t o = (size_t)node * 512 + ocoff + c;
    __half2 t0, t1;
    t0.x = __float2half_rn(acc.x); t0.y = __float2half_rn(acc.y);
    t1.x = __float2half_rn(acc.z); t1.y = __float2half_rn(acc.w);
    *(__half2*)(oF + o) = t0;
    *(__half2*)(oF + o + 2) = t1;
}

// ---------------- pool gather ----------------
__global__ void poolgather_k(const int* __restrict__ slist, const int* __restrict__ soff,
                             const float* __restrict__ hf,
                             f16* __restrict__ oF, int S) {
    int g = blockIdx.x * 4 + (threadIdx.x >> 6);
    if (g >= 2 * S) return;
    int part = (g >= S);
    int seg = g - part * S;
    int c = (threadIdx.x & 63) << 2;
    int s = soff[g], e = soff[g + 1];
    float4 acc = make_float4(0.f, 0.f, 0.f, 0.f);
    for (int k = s; k < e; k++) {
        int node = slist[k];
        float4 hv = *(const float4*)(hf + (size_t)node * 256 + c);
        acc.x += hv.x; acc.y += hv.y; acc.z += hv.z; acc.w += hv.w;
    }
    float inv = 1.0f / fmaxf((float)(e - s), 1.0f);
    acc.x *= inv; acc.y *= inv; acc.z *= inv; acc.w *= inv;
    size_t o = (size_t)seg * 512 + part * 256 + c;
    __half2 t0, t1;
    t0.x = __float2half_rn(acc.x); t0.y = __float2half_rn(acc.y);
    t1.x = __float2half_rn(acc.z); t1.y = __float2half_rn(acc.w);
    *(__half2*)(oF + o) = t0;
    *(__half2*)(oF + o + 2) = t1;
}

// ---------------- splits ----------------
// input x fp32 -> single f16 (activations)
__global__ void castA_k(const float* __restrict__ src, int Ks,
                        f16* __restrict__ dF, int dstride, int coff, long total4) {
    long gid = blockIdx.x * (long)blockDim.x + threadIdx.x;
    if (gid >= total4) return;
    long e = gid * 4;
    long r = e / Ks;
    int  c = (int)(e - r * Ks);
    float4 v = *(const float4*)(src + e);
    __half2 t0, t1;
    t0.x = __float2half_rn(v.x); t0.y = __float2half_rn(v.y);
    t1.x = __float2half_rn(v.z); t1.y = __float2half_rn(v.w);
    __half2* p = (__half2*)(dF + r * (long)dstride + coff + c);
    p[0] = t0; p[1] = t1;
}

// all 9 weight matrices -> transposed f16 hi/lo arena
__global__ void splitAllW_k(const float* __restrict__ w11, const float* __restrict__ w12,
                            const float* __restrict__ w21, const float* __restrict__ w22,
                            const float* __restrict__ m1w1, const float* __restrict__ m1w2,
                            const float* __restrict__ m2w1, const float* __restrict__ m2w2,
                            const float* __restrict__ mw1,
                            f16* __restrict__ dh, f16* __restrict__ dl) {
    int gid = blockIdx.x * blockDim.x + threadIdx.x;
    if (gid >= WTOT) return;
    float v; int dst;
    if (gid < 65536) {
        int l = gid, which = l >= 32768, g = l - which * 32768;
        int k = g >> 8, n = g & 255;
        v = which ? w12[g] : w11[g];
        dst = WC1 + (n + which * 256) * 128 + k;
    } else if (gid < 196608) {
        int l = gid - 65536, which = l >= 65536, g = l - which * 65536;
        int k = g >> 8, n = g & 255;
        v = which ? w22[g] : w21[g];
        dst = WC2 + (n + which * 256) * 256 + k;
    } else if (gid < 327680) {
        int g = gid - 196608;
        int k = g >> 8, n = g & 255;
        v = m1w1[g];
        dst = WM1A + n * 512 + k;
    } else if (gid < 393216) {
        int g = gid - 327680;
        int k = g >> 8, n = g & 255;
        v = m1w2[g];
        dst = WM1B + n * 256 + k;
    } else if (gid < 524288) {
        int g = gid - 393216;
        int k = g >> 8, n = g & 255;
        v = m2w1[g];
        dst = WM2A + n * 512 + k;
    } else if (gid < 589824) {
        int g = gid - 524288;
        int k = g >> 8, n = g & 255;
        v = m2w2[g];
        dst = WM2B + n * 256 + k;
    } else {
        int g = gid - 589824;
        int k = g >> 8, n = g & 255;
        v = mw1[g];
        dst = WHD + n * 512 + k;
    }
    f16 h, l;
    splithf(v, h, l);
    dh[dst] = h;
    dl[dst] = l;
}

// ---------------- head ----------------
__global__ void final_k(const float* __restrict__ hid, const float* __restrict__ w2,
                        const float* __restrict__ b2, float* __restrict__ out) {
    __shared__ float sh[DD];
    __shared__ float lg[CC];
    int s = blockIdx.x;
    int tid = threadIdx.x;
    sh[tid] = hid[(size_t)s * DD + tid];
    __syncthreads();
    int w = tid >> 5, lane = tid & 31;
    if (w < CC) {
        float sum = 0.0f;
        for (int k = lane; k < DD; k += 32) sum += sh[k] * w2[k * CC + w];
        #pragma unroll
        for (int o = 16; o > 0; o >>= 1) sum += __shfl_xor_sync(0xFFFFFFFFu, sum, o);
        if (lane == 0) lg[w] = sum + b2[w];
    }
    __syncthreads();
    if (tid == 0) {
        float mx = -1e30f;
        #pragma unroll
        for (int c = 0; c < CC; c++) mx = fmaxf(mx, lg[c]);
        float se = 0.0f;
        #pragma unroll
        for (int c = 0; c < CC; c++) se += expf(lg[c] - mx);
        float lse = mx + logf(se);
        #pragma unroll
        for (int c = 0; c < CC; c++) out[(size_t)s * CC + c] = lg[c] - lse;
    }
}

// ---------------- fp16 2-term double-buffered GEMM ----------------
// C = A(f16) @ (Wh + Wl)^T, fp32 accum. Epilogues:
// EPI=0 raw->C[r*512+c]; EPI=2 f16(relu(acc+b))->oF; EPI=3 f16(acc+b)->oF;
// EPI=4 C[r*256+c]=acc+b; EPI=5 relu variant
#define LDK2 40
#define STAGE_BYTES 30720   // A 10240 | Bh 10240 | Bl 10240

__device__ __forceinline__ void gemm_prefetch(
    char* smbase, int stage, int row, int hlf,
    const f16* A, int lda,
    const f16* BH, const f16* BL, int ldb,
    int bm, int bn, int M, int k0)
{
    int gra = bm + row;
    int szA = (gra < M) ? 16 : 0;
    if (gra >= M) gra = 0;
    const char* pA  = (const char*)(A + (size_t)gra * lda + k0) + hlf * 32;
    int grb = bn + row;
    const char* pBH = (const char*)(BH + (size_t)grb * ldb + k0) + hlf * 32;
    const char* pBL = (const char*)(BL + (size_t)grb * ldb + k0) + hlf * 32;
    uint32_t so = (uint32_t)__cvta_generic_to_shared(smbase + stage * STAGE_BYTES)
                  + row * (LDK2 * 2) + hlf * 32;
    cp16(so,              pA,       szA);  cp16(so + 16,          pA + 16,  szA);
    cp16(so + 10240,      pBH,      16);   cp16(so + 10240 + 16,  pBH + 16, 16);
    cp16(so + 20480,      pBL,      16);   cp16(so + 20480 + 16,  pBL + 16, 16);
}

template<int EPI>
__global__ void __launch_bounds__(256)
gemm_f16(const f16* __restrict__ A, int lda,
         const f16* __restrict__ BH, const f16* __restrict__ BL, int ldb,
         float* __restrict__ C,
         const float* __restrict__ bias,
         f16* __restrict__ oF, int ostride, int ocoff,
         int M, int K)
{
    extern __shared__ char sm_[];
    int tid = threadIdx.x, wid = tid >> 5, lane = tid & 31;
    int bm = blockIdx.y * 128, bn = blockIdx.x * 128;
    int wm = (wid & 3) * 32, wn = (wid >> 2) * 64;
    int idx = lane >> 3, lr = lane & 7;
    int row = tid >> 1, hlf = tid & 1;

    float acc[2][8][4];
    #pragma unroll
    for (int i = 0; i < 2; i++)
        #pragma unroll
        for (int j = 0; j < 8; j++)
            #pragma unroll
            for (int q = 0; q < 4; q++) acc[i][j][q] = 0.0f;

    int KT = K >> 5;
    gemm_prefetch(sm_, 0, row, hlf, A, lda, BH, BL, ldb, bm, bn, M, 0);
    asm volatile("cp.async.commit_group;");

    for (int kt = 0; kt < KT; kt++) {
        int s = kt & 1;
        if (kt + 1 < KT) {
            gemm_prefetch(sm_, s ^ 1, row, hlf, A, lda, BH, BL, ldb,
                          bm, bn, M, (kt + 1) << 5);
            asm volatile("cp.async.commit_group;");
            asm volatile("cp.async.wait_group 1;");
        } else {
            asm volatile("cp.async.wait_group 0;");
        }
        __syncthreads();

        const f16* sA  = (const f16*)(sm_ + s * STAGE_BYTES);
        const f16* sBh = (const f16*)(sm_ + s * STAGE_BYTES + 10240);
        const f16* sBl = (const f16*)(sm_ + s * STAGE_BYTES + 20480);

        #pragma unroll
        for (int ks = 0; ks < 2; ks++) {
            int kb = ks * 16;
            uint32_t a[2][4];
            #pragma unroll
            for (int mf = 0; mf < 2; mf++) {
                int rr = wm + mf * 16 + (idx & 1) * 8 + lr;
                int cc = kb + (idx >> 1) * 8;
                ldm_x4(a[mf], &sA[rr * LDK2 + cc]);
            }
            uint32_t bh[4][4], bl[4][4];
            #pragma unroll
            for (int bg = 0; bg < 4; bg++) {
                int rr = wn + bg * 16 + (idx >> 1) * 8 + lr;
                int cc = kb + (idx & 1) * 8;
                ldm_x4(bh[bg], &sBh[rr * LDK2 + cc]);
                ldm_x4(bl[bg], &sBl[rr * LDK2 + cc]);
            }
            #pragma unroll
            for (int mf = 0; mf < 2; mf++)
                #pragma unroll
                for (int ng = 0; ng < 8; ng++) {
                    int bg = ng >> 1, pr = (ng & 1) * 2;
                    mma16816(acc[mf][ng], a[mf], bh[bg][pr], bh[bg][pr + 1]);
                    mma16816(acc[mf][ng], a[mf], bl[bg][pr], bl[bg][pr + 1]);
                }
        }
        __syncthreads();
    }

    // ---- epilogue ----
    int r0 = bm + wm + (lane >> 2);
    int lc0 = wn + (lane & 3) * 2;
    #pragma unroll
    for (int mf = 0; mf < 2; mf++) {
        #pragma unroll
        for (int hf2 = 0; hf2 < 2; hf2++) {
            int r = r0 + mf * 16 + hf2 * 8;
            if (r >= M) continue;
            #pragma unroll
            for (int ng = 0; ng < 8; ng++) {
                int lc = lc0 + ng * 8;
                int c = bn + lc;
                float v0 = acc[mf][ng][hf2 * 2 + 0];
                float v1 = acc[mf][ng][hf2 * 2 + 1];
                if (EPI == 0) {
                    float2 st; st.x = v0; st.y = v1;
                    *(float2*)(C + (size_t)r * 512 + c) = st;
                } else if (EPI == 2 || EPI == 3) {
                    v0 += bias[c]; v1 += bias[c + 1];
                    if (EPI == 2) { v0 = fmaxf(v0, 0.f); v1 = fmaxf(v1, 0.f); }
                    __half2 t;
                    t.x = __float2half_rn(v0); t.y = __float2half_rn(v1);
                    *(__half2*)(oF + (size_t)r * ostride + ocoff + c) = t;
                } else {
                    v0 += bias[c]; v1 += bias[c + 1];
                    if (EPI == 5) { v0 = fmaxf(v0, 0.f); v1 = fmaxf(v1, 0.f); }
                    float2 st; st.x = v0; st.y = v1;
                    *(float2*)(C + (size_t)r * 256 + c) = st;
                }
            }
        }
    }
}

// ---------------- launch ----------------
#define SMEM_GEMM (2 * STAGE_BYTES)

extern "C" void kernel_launch(void* const* d_in, const int* in_sizes, int n_in,
                              void* d_out, int out_size) {
    const float* x    = (const float*)d_in[0];
    const int*   e1   = (const int*)d_in[1];
    const int*   e2   = (const int*)d_in[2];
    const int*   i1   = (const int*)d_in[3];
    const int*   i2   = (const int*)d_in[4];
    const float* w11  = (const float*)d_in[5];
    const float* b11  = (const float*)d_in[6];
    const float* w12  = (const float*)d_in[7];
    const float* b12  = (const float*)d_in[8];
    const float* w21  = (const float*)d_in[9];
    const float* b21  = (const float*)d_in[10];
    const float* w22  = (const float*)d_in[11];
    const float* b22  = (const float*)d_in[12];
    const float* m1w1 = (const float*)d_in[13];
    const float* m1b1 = (const float*)d_in[14];
    const float* m1w2 = (const float*)d_in[15];
    const float* m1b2 = (const float*)d_in[16];
    const float* m2w1 = (const float*)d_in[17];
    const float* m2b1 = (const float*)d_in[18];
    const float* m2w2 = (const float*)d_in[19];
    const float* m2b2 = (const float*)d_in[20];
    const float* mw1  = (const float*)d_in[21];
    const float* mb1  = (const float*)d_in[22];
    const float* mw2  = (const float*)d_in[23];
    const float* mb2  = (const float*)d_in[24];
    float* out = (float*)d_out;

    int Nn = in_sizes[0] / FIN;
    int E1 = in_sizes[1] / 2;
    int E2 = in_sizes[2] / 2;
    int S  = out_size / CC;

    float* base = nullptr;
    cudaGetSymbolAddress((void**)&base, g_buf);
    float* h    = base + OFF_H;
    float* hf   = base + OFF_HF;
    float* hid2 = base + OFF_HID2;
    float* dis1 = base + OFF_DIS1;
    float* dis2 = base + OFF_DIS2;
    int* cc     = (int*)(base + OFF_CC);
    int* sc     = (int*)(base + OFF_SC);
    int* bsn    = (int*)(base + OFF_BSN);
    int* bss    = (int*)(base + OFF_BSS);
    int* coff   = (int*)(base + OFF_COFF);
    int* ccur   = (int*)(base + OFF_CCUR);
    int* soff   = (int*)(base + OFF_SOFF);
    int* scur   = (int*)(base + OFF_SCUR);
    int* csr    = (int*)(base + OFF_CSR);
    int* slist  = (int*)(base + OFF_SLIST);
    f16* XF = (f16*)(base + OFF_XF);
    f16* YF = (f16*)(base + OFF_YF);
    f16* WH = (f16*)(base + OFF_WH);
    f16* WL = (f16*)(base + OFF_WL);

    cudaFuncSetAttribute(gemm_f16<0>, cudaFuncAttributeMaxDynamicSharedMemorySize, SMEM_GEMM);
    cudaFuncSetAttribute(gemm_f16<2>, cudaFuncAttributeMaxDynamicSharedMemorySize, SMEM_GEMM);
    cudaFuncSetAttribute(gemm_f16<3>, cudaFuncAttributeMaxDynamicSharedMemorySize, SMEM_GEMM);
    cudaFuncSetAttribute(gemm_f16<4>, cudaFuncAttributeMaxDynamicSharedMemorySize, SMEM_GEMM);
    cudaFuncSetAttribute(gemm_f16<5>, cudaFuncAttributeMaxDynamicSharedMemorySize, SMEM_GEMM);

    const int T = 256;
    unsigned gy  = (unsigned)((Nn + 127) / 128);
    unsigned gys = (unsigned)((S + 127) / 128);
    dim3 g512(4, gy), g256(2, gy), gh(2, gys);
    unsigned gGat = (unsigned)((Nn + 7) / 8);
    unsigned gPool = (unsigned)((2 * S + 3) / 4);
    int nbN = (2 * Nn + SCAN_B - 1) / SCAN_B;
    int nbS = (2 * S + SCAN_B - 1) / SCAN_B;
    int nz = (int)(OFF_COFF - OFF_CC);

    // ---- prologue: zero + node/segment CSR build ----
    zero_k<<<(nz + T - 1) / T, T>>>(base + OFF_CC, nz);
    countall_k<<<(E1 + E2 + Nn + T - 1) / T, T>>>(e1, E1, e2, E2, i1, i2, Nn, S, cc, sc);
    blocksum_k<<<nbN, SCAN_B>>>(cc, bsn, 2 * Nn);
    blocksum_k<<<nbS, SCAN_B>>>(sc, bss, 2 * S);
    scanbsum_k<<<1, 32>>>(bsn, nbN, coff + 2 * Nn);
    scanbsum_k<<<1, 32>>>(bss, nbS, soff + 2 * S);
    scanblock_k<<<nbN, SCAN_B>>>(cc, bsn, coff, ccur, 2 * Nn);
    scanblock_k<<<nbS, SCAN_B>>>(sc, bss, soff, scur, 2 * S);
    disint_k<<<(Nn + T - 1) / T, T>>>(cc, dis1, dis2, Nn);
    placeboth_k<<<(E1 + E2 + T - 1) / T, T>>>(e1, E1, e2, E2, Nn, ccur, csr);
    placeseg_k<<<(Nn + T - 1) / T, T>>>(i1, i2, Nn, S, scur, slist);

    // ---- casts/splits: input x (f16) + all weights (f16 hi/lo) ----
    long t4 = (long)Nn * FIN / 4;
    castA_k<<<(unsigned)((t4 + T - 1) / T), T>>>(x, FIN, XF, 512, 0, t4);
    splitAllW_k<<<(WTOT + T - 1) / T, T>>>(w11, w12, w21, w22, m1w1, m1w2, m2w1, m2w2, mw1, WH, WL);

    // ---- layer 1: dual conv GEMM + column-blocked gathers ----
    gemm_f16<0><<<g512, 256, SMEM_GEMM>>>(XF, 512, WH + WC1, WL + WC1, FIN,
        h, nullptr, nullptr, 0, 0, Nn, FIN);
    gather_k<<<gGat, T>>>(csr, coff,      dis1, h,       b11, XF, 0,   0,   Nn);
    gather_k<<<gGat, T>>>(csr, coff,      dis1, h,       b11, XF, 0,   128, Nn);
    gather_k<<<gGat, T>>>(csr, coff + Nn, dis2, h + 256, b12, XF, 256, 0,   Nn);
    gather_k<<<gGat, T>>>(csr, coff + Nn, dis2, h + 256, b12, XF, 256, 128, Nn);
    // ---- mlp_1 ----
    gemm_f16<2><<<g256, 256, SMEM_GEMM>>>(XF, 512, WH + WM1A, WL + WM1A, 512,
        nullptr, m1b1, YF, 256, 0, Nn, 512);
    gemm_f16<3><<<g256, 256, SMEM_GEMM>>>(YF, 256, WH + WM1B, WL + WM1B, 256,
        nullptr, m1b2, XF, 512, 0, Nn, 256);

    // ---- layer 2: dual conv GEMM + column-blocked gathers ----
    gemm_f16<0><<<g512, 256, SMEM_GEMM>>>(XF, 512, WH + WC2, WL + WC2, DD,
        h, nullptr, nullptr, 0, 0, Nn, DD);
    gather_k<<<gGat, T>>>(csr, coff,      dis1, h,       b21, XF, 0,   0,   Nn);
    gather_k<<<gGat, T>>>(csr, coff,      dis1, h,       b21, XF, 0,   128, Nn);
    gather_k<<<gGat, T>>>(csr, coff + Nn, dis2, h + 256, b22, XF, 256, 0,   Nn);
    gather_k<<<gGat, T>>>(csr, coff + Nn, dis2, h + 256, b22, XF, 256, 128, Nn);
    // ---- mlp_2 ----
    gemm_f16<2><<<g256, 256, SMEM_GEMM>>>(XF, 512, WH + WM2A, WL + WM2A, 512,
        nullptr, m2b1, YF, 256, 0, Nn, 512);
    gemm_f16<4><<<g256, 256, SMEM_GEMM>>>(YF, 256, WH + WM2B, WL + WM2B, 256,
        hf, m2b2, nullptr, 0, 0, Nn, 256);

    // ---- pooling ----
    poolgather_k<<<gPool, T>>>(slist, soff, hf, XF, S);

    // ---- head ----
    gemm_f16<5><<<gh, 256, SMEM_GEMM>>>(XF, 512, WH + WHD, WL + WHD, 512,
        hid2, mb1, nullptr, 0, 0, S, 512);
    final_k<<<S, DD>>>(hid2, mw2, mb2, out);
}

// round 14
// speedup vs baseline: 1.2202x; 1.2202x over previous
#include <cuda_runtime.h>
#include <cuda_bf16.h>
#include <cuda_fp16.h>
#include <math.h>
#include <stdint.h>
#include <cstdint>

// ---------------- Problem constants ----------------
#define DD 256
#define FIN 128
#define CC 7

typedef __nv_bfloat16 bf16;
typedef __half f16;

// ---------------- Scratch layout (float offsets) ----------------
#define OFF_H     0L             // f16 [M,512] conv GEMM out (25.6M floats reserved)
#define OFF_HF    51200000L      // fp32 [M,256]
#define OFF_XH    76800000L      // bf16 [M,512] hi
#define OFF_XL    102400000L
#define OFF_YH    128000000L     // bf16 [M,256] hi
#define OFF_YL    140800000L
#define OFF_WH    153600000L     // bf16 weight arena hi (720896 bf16)
#define OFF_WL    154000000L
#define OFF_HID2  154400000L
#define OFF_DIS1  155680000L
#define OFF_DIS2  155780000L
// ---- zero block start ----
#define OFF_CC    155880000L     // int[2N]
#define OFF_SC    156080000L     // int[2S]
#define OFF_BSN   156090000L     // int[256]
#define OFF_BSS   156090256L     // int[16]
// ---- zero block end ----
#define OFF_COFF  156090272L     // int[2N+1]
#define OFF_CCUR  156290276L
#define OFF_SOFF  156490276L     // int[2S+1]
#define OFF_SCUR  156500280L
#define OFF_CSR   156510280L     // int[E1+E2]
#define OFF_SLIST 158110280L     // int[2N]
#define SCRATCH_TOTAL 158310280L

// weight arena offsets (bf16 elements)
#define WC1  0
#define WC2  65536
#define WM1A 196608
#define WM1B 327680
#define WM2A 393216
#define WM2B 524288
#define WHD  589824
#define WTOT 720896

__device__ float g_buf[SCRATCH_TOTAL];

// ---------------- helpers ----------------
__device__ __forceinline__ void splitbf(float v, bf16& h, bf16& l) {
    h = __float2bfloat16(v);
    l = __float2bfloat16(v - __bfloat162float(h));
}

__device__ __forceinline__ void ldm_x4(uint32_t r[4], const void* p) {
    uint32_t addr = (uint32_t)__cvta_generic_to_shared(p);
    asm volatile("ldmatrix.sync.aligned.m8n8.x4.shared.b16 {%0,%1,%2,%3}, [%4];"
                 : "=r"(r[0]), "=r"(r[1]), "=r"(r[2]), "=r"(r[3]) : "r"(addr));
}

__device__ __forceinline__ void mma16816(float c[4], const uint32_t a[4],
                                         uint32_t b0, uint32_t b1) {
    asm volatile(
        "mma.sync.aligned.m16n8k16.row.col.f32.bf16.bf16.f32 "
        "{%0,%1,%2,%3}, {%4,%5,%6,%7}, {%8,%9}, {%0,%1,%2,%3};"
        : "+f"(c[0]), "+f"(c[1]), "+f"(c[2]), "+f"(c[3])
        : "r"(a[0]), "r"(a[1]), "r"(a[2]), "r"(a[3]), "r"(b0), "r"(b1));
}

__device__ __forceinline__ void cp16(uint32_t s, const void* g, int sz) {
    asm volatile("cp.async.cg.shared.global [%0], [%1], 16, %2;"
                 :: "r"(s), "l"(g), "r"(sz));
}

// ---------------- prologue kernels ----------------
#define SCAN_B 1024

__global__ void zero_k(float* __restrict__ p, int n) {
    int i = blockIdx.x * blockDim.x + threadIdx.x;
    if (i < n) p[i] = 0.0f;
}

__global__ void countall_k(const int* __restrict__ e1, int E1,
                           const int* __restrict__ e2, int E2,
                           const int* __restrict__ i1, const int* __restrict__ i2,
                           int Nn, int S,
                           int* __restrict__ cc, int* __restrict__ sc) {
    int i = blockIdx.x * blockDim.x + threadIdx.x;
    if (i < E1) atomicAdd(&cc[e1[E1 + i]], 1);
    else if (i < E1 + E2) atomicAdd(&cc[Nn + e2[E2 + (i - E1)]], 1);
    else {
        int j = i - E1 - E2;
        if (j < Nn) {
            atomicAdd(&sc[i1[j]], 1);
            atomicAdd(&sc[S + i2[j]], 1);
        }
    }
}

__global__ void blocksum_k(const int* __restrict__ cnt, int* __restrict__ bsum, int n) {
    int i = blockIdx.x * SCAN_B + threadIdx.x;
    int v = (i < n) ? cnt[i] : 0;
    #pragma unroll
    for (int o = 16; o > 0; o >>= 1) v += __shfl_xor_sync(0xFFFFFFFFu, v, o);
    if ((threadIdx.x & 31) == 0) atomicAdd(&bsum[blockIdx.x], v);
}

__global__ void scanbsum_k(int* __restrict__ bsum, int nb, int* __restrict__ off_n) {
    if (threadIdx.x == 0) {
        int acc = 0;
        for (int i = 0; i < nb; i++) { int v = bsum[i]; bsum[i] = acc; acc += v; }
        *off_n = acc;
    }
}

__global__ void scanblock_k(const int* __restrict__ cnt, const int* __restrict__ bsum,
                            int* __restrict__ off, int* __restrict__ cur, int n) {
    __shared__ int sw[32];
    int tid = threadIdx.x, lane = tid & 31, wid = tid >> 5;
    int i = blockIdx.x * SCAN_B + tid;
    int v = (i < n) ? cnt[i] : 0;
    int inc = v;
    #pragma unroll
    for (int o = 1; o < 32; o <<= 1) {
        int t = __shfl_up_sync(0xFFFFFFFFu, inc, o);
        if (lane >= o) inc += t;
    }
    if (lane == 31) sw[wid] = inc;
    __syncthreads();
    if (wid == 0) {
        int t = sw[lane];
        int ti = t;
        #pragma unroll
        for (int o = 1; o < 32; o <<= 1) {
            int u = __shfl_up_sync(0xFFFFFFFFu, ti, o);
            if (lane >= o) ti += u;
        }
        sw[lane] = ti - t;
    }
    __syncthreads();
    int excl = inc - v + sw[wid] + bsum[blockIdx.x];
    if (i < n) { off[i] = excl; cur[i] = excl; }
}

__global__ void disint_k(const int* __restrict__ cc,
                         float* __restrict__ d1, float* __restrict__ d2, int Nn) {
    int i = blockIdx.x * blockDim.x + threadIdx.x;
    if (i < Nn) {
        d1[i] = rsqrtf((float)cc[i] + 1.0f);
        d2[i] = rsqrtf((float)cc[Nn + i] + 1.0f);
    }
}

__global__ void placeboth_k(const int* __restrict__ e1, int E1,
                            const int* __restrict__ e2, int E2, int Nn,
                            int* __restrict__ cur, int* __restrict__ csr) {
    int i = blockIdx.x * blockDim.x + threadIdx.x;
    if (i < E1) {
        int pos = atomicAdd(&cur[e1[E1 + i]], 1);
        csr[pos] = e1[i];
    } else if (i < E1 + E2) {
        int j = i - E1;
        int pos = atomicAdd(&cur[Nn + e2[E2 + j]], 1);
        csr[pos] = e2[j];
    }
}

__global__ void placeseg_k(const int* __restrict__ i1, const int* __restrict__ i2,
                           int Nn, int S,
                           int* __restrict__ scur, int* __restrict__ slist) {
    int i = blockIdx.x * blockDim.x + threadIdx.x;
    if (i < Nn) {
        int p1 = atomicAdd(&scur[i1[i]], 1);
        slist[p1] = i;
        int p2 = atomicAdd(&scur[S + i2[i]], 1);
        slist[p2] = i;
    }
}

// ---------------- gather conv (h in fp16, 51MB working set -> L2-resident) ----
// X[node, ocoff+c] = splitbf(relu(bias + d^2 h_i + sum coef h_j))
__global__ void gather_k(const int* __restrict__ csr, const int* __restrict__ off,
                         const float* __restrict__ dis,
                         const f16* __restrict__ h,       // pre-offset, stride 512
                         const float* __restrict__ bias,
                         bf16* __restrict__ oH, bf16* __restrict__ oL,
                         int ocoff, int Nn) {
    int node = blockIdx.x * 4 + (threadIdx.x >> 6);
    if (node >= Nn) return;
    int c = (threadIdx.x & 63) << 2;
    float di = dis[node];
    float d2 = di * di;
    const __half2* hp = (const __half2*)(h + (size_t)node * 512 + c);
    float2 s0 = __half22float2(hp[0]);
    float2 s1 = __half22float2(hp[1]);
    float4 bv = *(const float4*)(bias + c);
    float4 acc;
    acc.x = bv.x + d2 * s0.x; acc.y = bv.y + d2 * s0.y;
    acc.z = bv.z + d2 * s1.x; acc.w = bv.w + d2 * s1.y;
    int s = off[node], e = off[node + 1];
    for (int k = s; k < e; k++) {
        int j = csr[k];
        float coef = di * dis[j];
        const __half2* hj = (const __half2*)(h + (size_t)j * 512 + c);
        float2 f0 = __half22float2(hj[0]);
        float2 f1 = __half22float2(hj[1]);
        acc.x += coef * f0.x; acc.y += coef * f0.y;
        acc.z += coef * f1.x; acc.w += coef * f1.y;
    }
    acc.x = fmaxf(acc.x, 0.f); acc.y = fmaxf(acc.y, 0.f);
    acc.z = fmaxf(acc.z, 0.f); acc.w = fmaxf(acc.w, 0.f);
    bf16 h0,l0,h1,l1,h2,l2,h3,l3;
    splitbf(acc.x,h0,l0); splitbf(acc.y,h1,l1);
    splitbf(acc.z,h2,l2); splitbf(acc.w,h3,l3);
    size_t o = (size_t)node * 512 + ocoff + c;
    __nv_bfloat162 t;
    t.x=h0; t.y=h1; *(__nv_bfloat162*)(oH + o) = t;
    t.x=h2; t.y=h3; *(__nv_bfloat162*)(oH + o + 2) = t;
    t.x=l0; t.y=l1; *(__nv_bfloat162*)(oL + o) = t;
    t.x=l2; t.y=l3; *(__nv_bfloat162*)(oL + o + 2) = t;
}

// ---------------- pool gather ----------------
__global__ void poolgather_k(const int* __restrict__ slist, const int* __restrict__ soff,
                             const float* __restrict__ hf,
                             bf16* __restrict__ oH, bf16* __restrict__ oL, int S) {
    int g = blockIdx.x * 4 + (threadIdx.x >> 6);
    if (g >= 2 * S) return;
    int part = (g >= S);
    int seg = g - part * S;
    int c = (threadIdx.x & 63) << 2;
    int s = soff[g], e = soff[g + 1];
    float4 acc = make_float4(0.f, 0.f, 0.f, 0.f);
    for (int k = s; k < e; k++) {
        int node = slist[k];
        float4 hv = *(const float4*)(hf + (size_t)node * 256 + c);
        acc.x += hv.x; acc.y += hv.y; acc.z += hv.z; acc.w += hv.w;
    }
    float inv = 1.0f / fmaxf((float)(e - s), 1.0f);
    acc.x *= inv; acc.y *= inv; acc.z *= inv; acc.w *= inv;
    bf16 h0,l0,h1,l1,h2,l2,h3,l3;
    splitbf(acc.x,h0,l0); splitbf(acc.y,h1,l1);
    splitbf(acc.z,h2,l2); splitbf(acc.w,h3,l3);
    size_t o = (size_t)seg * 512 + part * 256 + c;
    __nv_bfloat162 t;
    t.x=h0; t.y=h1; *(__nv_bfloat162*)(oH + o) = t;
    t.x=h2; t.y=h3; *(__nv_bfloat162*)(oH + o + 2) = t;
    t.x=l0; t.y=l1; *(__nv_bfloat162*)(oL + o) = t;
    t.x=l2; t.y=l3; *(__nv_bfloat162*)(oL + o + 2) = t;
}

// ---------------- splits ----------------
template<bool RELU>
__global__ void splitA_k(const float* __restrict__ src, int Ks,
                         bf16* __restrict__ dh, bf16* __restrict__ dl,
                         int dstride, int coff, long total4) {
    long gid = blockIdx.x * (long)blockDim.x + threadIdx.x;
    if (gid >= total4) return;
    long e = gid * 4;
    long r = e / Ks;
    int  c = (int)(e - r * Ks);
    float4 v = *(const float4*)(src + e);
    if (RELU) {
        v.x = fmaxf(v.x, 0.f); v.y = fmaxf(v.y, 0.f);
        v.z = fmaxf(v.z, 0.f); v.w = fmaxf(v.w, 0.f);
    }
    bf16 h0,l0,h1,l1,h2,l2,h3,l3;
    splitbf(v.x,h0,l0); splitbf(v.y,h1,l1); splitbf(v.z,h2,l2); splitbf(v.w,h3,l3);
    __nv_bfloat162* ph = (__nv_bfloat162*)(dh + r * (long)dstride + coff + c);
    __nv_bfloat162* pl = (__nv_bfloat162*)(dl + r * (long)dstride + coff + c);
    __nv_bfloat162 t;
    t.x=h0; t.y=h1; ph[0]=t;  t.x=h2; t.y=h3; ph[1]=t;
    t.x=l0; t.y=l1; pl[0]=t;  t.x=l2; t.y=l3; pl[1]=t;
}

__global__ void splitAllW_k(const float* __restrict__ w11, const float* __restrict__ w12,
                            const float* __restrict__ w21, const float* __restrict__ w22,
                            const float* __restrict__ m1w1, const float* __restrict__ m1w2,
                            const float* __restrict__ m2w1, const float* __restrict__ m2w2,
                            const float* __restrict__ mw1,
                            bf16* __restrict__ dh, bf16* __restrict__ dl) {
    int gid = blockIdx.x * blockDim.x + threadIdx.x;
    if (gid >= WTOT) return;
    float v; int dst;
    if (gid < 65536) {
        int l = gid, which = l >= 32768, g = l - which * 32768;
        int k = g >> 8, n = g & 255;
        v = which ? w12[g] : w11[g];
        dst = WC1 + (n + which * 256) * 128 + k;
    } else if (gid < 196608) {
        int l = gid - 65536, which = l >= 65536, g = l - which * 65536;
        int k = g >> 8, n = g & 255;
        v = which ? w22[g] : w21[g];
        dst = WC2 + (n + which * 256) * 256 + k;
    } else if (gid < 327680) {
        int g = gid - 196608;
        int k = g >> 8, n = g & 255;
        v = m1w1[g];
        dst = WM1A + n * 512 + k;
    } else if (gid < 393216) {
        int g = gid - 327680;
        int k = g >> 8, n = g & 255;
        v = m1w2[g];
        dst = WM1B + n * 256 + k;
    } else if (gid < 524288) {
        int g = gid - 393216;
        int k = g >> 8, n = g & 255;
        v = m2w1[g];
        dst = WM2A + n * 512 + k;
    } else if (gid < 589824) {
        int g = gid - 524288;
        int k = g >> 8, n = g & 255;
        v = m2w2[g];
        dst = WM2B + n * 256 + k;
    } else {
        int g = gid - 589824;
        int k = g >> 8, n = g & 255;
        v = mw1[g];
        dst = WHD + n * 512 + k;
    }
    bf16 h, l;
    splitbf(v, h, l);
    dh[dst] = h;
    dl[dst] = l;
}

// ---------------- head ----------------
__global__ void final_k(const float* __restrict__ hid, const float* __restrict__ w2,
                        const float* __restrict__ b2, float* __restrict__ out) {
    __shared__ float sh[DD];
    __shared__ float lg[CC];
    int s = blockIdx.x;
    int tid = threadIdx.x;
    sh[tid] = hid[(size_t)s * DD + tid];
    __syncthreads();
    int w = tid >> 5, lane = tid & 31;
    if (w < CC) {
        float sum = 0.0f;
        for (int k = lane; k < DD; k += 32) sum += sh[k] * w2[k * CC + w];
        #pragma unroll
        for (int o = 16; o > 0; o >>= 1) sum += __shfl_xor_sync(0xFFFFFFFFu, sum, o);
        if (lane == 0) lg[w] = sum + b2[w];
    }
    __syncthreads();
    if (tid == 0) {
        float mx = -1e30f;
        #pragma unroll
        for (int c = 0; c < CC; c++) mx = fmaxf(mx, lg[c]);
        float se = 0.0f;
        #pragma unroll
        for (int c = 0; c < CC; c++) se += expf(lg[c] - mx);
        float lse = mx + logf(se);
        #pragma unroll
        for (int c = 0; c < CC; c++) out[(size_t)s * CC + c] = lg[c] - lse;
    }
}

// ---------------- bf16 3-term double-buffered GEMM ----------------
// EPI=1 RAW_F16: ((f16*)C)[r*512+c] = f16(acc)
// EPI=2 split(relu(acc+b))->oH/oL   EPI=3 split(acc+b)->oH/oL
// EPI=4 C[r*256+c]=acc+b            EPI=5 relu variant
#define LDK2 40
#define STAGE_BYTES 40960

__device__ __forceinline__ void gemm_prefetch(
    char* smbase, int stage, int row, int hlf,
    const bf16* AH, const bf16* AL, int lda,
    const bf16* BH, const bf16* BL, int ldb,
    int bm, int bn, int M, int k0)
{
    int gra = bm + row;
    int szA = (gra < M) ? 16 : 0;
    if (gra >= M) gra = 0;
    const char* pAH = (const char*)(AH + (size_t)gra * lda + k0) + hlf * 32;
    const char* pAL = (const char*)(AL + (size_t)gra * lda + k0) + hlf * 32;
    int grb = bn + row;
    const char* pBH = (const char*)(BH + (size_t)grb * ldb + k0) + hlf * 32;
    const char* pBL = (const char*)(BL + (size_t)grb * ldb + k0) + hlf * 32;
    uint32_t so = (uint32_t)__cvta_generic_to_shared(smbase + stage * STAGE_BYTES)
                  + row * (LDK2 * 2) + hlf * 32;
    cp16(so,              pAH,      szA);  cp16(so + 16,          pAH + 16, szA);
    cp16(so + 10240,      pAL,      szA);  cp16(so + 10240 + 16,  pAL + 16, szA);
    cp16(so + 20480,      pBH,      16);   cp16(so + 20480 + 16,  pBH + 16, 16);
    cp16(so + 30720,      pBL,      16);   cp16(so + 30720 + 16,  pBL + 16, 16);
}

template<int EPI>
__global__ void __launch_bounds__(256)
gemm_bf16(const bf16* __restrict__ AH, const bf16* __restrict__ AL, int lda,
          const bf16* __restrict__ BH, const bf16* __restrict__ BL, int ldb,
          float* __restrict__ C,
          const float* __restrict__ bias,
          bf16* __restrict__ oH, bf16* __restrict__ oL, int ostride, int ocoff,
          int M, int K)
{
    extern __shared__ char sm_[];
    int tid = threadIdx.x, wid = tid >> 5, lane = tid & 31;
    int bm = blockIdx.y * 128, bn = blockIdx.x * 128;
    int wm = (wid & 3) * 32, wn = (wid >> 2) * 64;
    int idx = lane >> 3, lr = lane & 7;
    int row = tid >> 1, hlf = tid & 1;

    float acc[2][8][4];
    #pragma unroll
    for (int i = 0; i < 2; i++)
        #pragma unroll
        for (int j = 0; j < 8; j++)
            #pragma unroll
            for (int q = 0; q < 4; q++) acc[i][j][q] = 0.0f;

    int KT = K >> 5;
    gemm_prefetch(sm_, 0, row, hlf, AH, AL, lda, BH, BL, ldb, bm, bn, M, 0);
    asm volatile("cp.async.commit_group;");

    for (int kt = 0; kt < KT; kt++) {
        int s = kt & 1;
        if (kt + 1 < KT) {
            gemm_prefetch(sm_, s ^ 1, row, hlf, AH, AL, lda, BH, BL, ldb,
                          bm, bn, M, (kt + 1) << 5);
            asm volatile("cp.async.commit_group;");
            asm volatile("cp.async.wait_group 1;");
        } else {
            asm volatile("cp.async.wait_group 0;");
        }
        __syncthreads();

        const bf16* sAh = (const bf16*)(sm_ + s * STAGE_BYTES);
        const bf16* sAl = (const bf16*)(sm_ + s * STAGE_BYTES + 10240);
        const bf16* sBh = (const bf16*)(sm_ + s * STAGE_BYTES + 20480);
        const bf16* sBl = (const bf16*)(sm_ + s * STAGE_BYTES + 30720);

        #pragma unroll
        for (int ks = 0; ks < 2; ks++) {
            int kb = ks * 16;
            uint32_t ah[2][4], al[2][4];
            #pragma unroll
            for (int mf = 0; mf < 2; mf++) {
                int rr = wm + mf * 16 + (idx & 1) * 8 + lr;
                int cc2 = kb + (idx >> 1) * 8;
                ldm_x4(ah[mf], &sAh[rr * LDK2 + cc2]);
                ldm_x4(al[mf], &sAl[rr * LDK2 + cc2]);
            }
            uint32_t bh[4][4], bl[4][4];
            #pragma unroll
            for (int bg = 0; bg < 4; bg++) {
                int rr = wn + bg * 16 + (idx >> 1) * 8 + lr;
                int cc2 = kb + (idx & 1) * 8;
                ldm_x4(bh[bg], &sBh[rr * LDK2 + cc2]);
                ldm_x4(bl[bg], &sBl[rr * LDK2 + cc2]);
            }
            #pragma unroll
            for (int mf = 0; mf < 2; mf++)
                #pragma unroll
                for (int ng = 0; ng < 8; ng++) {
                    int bg = ng >> 1, pr = (ng & 1) * 2;
                    mma16816(acc[mf][ng], ah[mf], bh[bg][pr], bh[bg][pr + 1]);
                    mma16816(acc[mf][ng], ah[mf], bl[bg][pr], bl[bg][pr + 1]);
                    mma16816(acc[mf][ng], al[mf], bh[bg][pr], bh[bg][pr + 1]);
                }
        }
        __syncthreads();
    }

    // ---- epilogue ----
    int r0 = bm + wm + (lane >> 2);
    int lc0 = wn + (lane & 3) * 2;
    #pragma unroll
    for (int mf = 0; mf < 2; mf++) {
        #pragma unroll
        for (int hf2 = 0; hf2 < 2; hf2++) {
            int r = r0 + mf * 16 + hf2 * 8;
            if (r >= M) continue;
            #pragma unroll
            for (int ng = 0; ng < 8; ng++) {
                int lc = lc0 + ng * 8;
                int c = bn + lc;
                float v0 = acc[mf][ng][hf2 * 2 + 0];
                float v1 = acc[mf][ng][hf2 * 2 + 1];
                if (EPI == 1) {
                    __half2 t;
                    t.x = __float2half_rn(v0); t.y = __float2half_rn(v1);
                    *(__half2*)((f16*)C + (size_t)r * 512 + c) = t;
                } else if (EPI == 2 || EPI == 3) {
                    v0 += bias[c]; v1 += bias[c + 1];
                    if (EPI == 2) { v0 = fmaxf(v0, 0.f); v1 = fmaxf(v1, 0.f); }
                    bf16 h0, l0, h1, l1;
                    splitbf(v0, h0, l0); splitbf(v1, h1, l1);
                    __nv_bfloat162 th; th.x = h0; th.y = h1;
                    __nv_bfloat162 tl; tl.x = l0; tl.y = l1;
                    size_t o = (size_t)r * ostride + ocoff + c;
                    *(__nv_bfloat162*)(oH + o) = th;
                    *(__nv_bfloat162*)(oL + o) = tl;
                } else {
                    v0 += bias[c]; v1 += bias[c + 1];
                    if (EPI == 5) { v0 = fmaxf(v0, 0.f); v1 = fmaxf(v1, 0.f); }
                    float2 st; st.x = v0; st.y = v1;
                    *(float2*)(C + (size_t)r * 256 + c) = st;
                }
            }
        }
    }
}

// ---------------- launch ----------------
#define SMEM_GEMM (2 * STAGE_BYTES)

extern "C" void kernel_launch(void* const* d_in, const int* in_sizes, int n_in,
                              void* d_out, int out_size) {
    const float* x    = (const float*)d_in[0];
    const int*   e1   = (const int*)d_in[1];
    const int*   e2   = (const int*)d_in[2];
    const int*   i1   = (const int*)d_in[3];
    const int*   i2   = (const int*)d_in[4];
    const float* w11  = (const float*)d_in[5];
    const float* b11  = (const float*)d_in[6];
    const float* w12  = (const float*)d_in[7];
    const float* b12  = (const float*)d_in[8];
    const float* w21  = (const float*)d_in[9];
    const float* b21  = (const float*)d_in[10];
    const float* w22  = (const float*)d_in[11];
    const float* b22  = (const float*)d_in[12];
    const float* m1w1 = (const float*)d_in[13];
    const float* m1b1 = (const float*)d_in[14];
    const float* m1w2 = (const float*)d_in[15];
    const float* m1b2 = (const float*)d_in[16];
    const float* m2w1 = (const float*)d_in[17];
    const float* m2b1 = (const float*)d_in[18];
    const float* m2w2 = (const float*)d_in[19];
    const float* m2b2 = (const float*)d_in[20];
    const float* mw1  = (const float*)d_in[21];
    const float* mb1  = (const float*)d_in[22];
    const float* mw2  = (const float*)d_in[23];
    const float* mb2  = (const float*)d_in[24];
    float* out = (float*)d_out;

    int Nn = in_sizes[0] / FIN;
    int E1 = in_sizes[1] / 2;
    int E2 = in_sizes[2] / 2;
    int S  = out_size / CC;

    float* base = nullptr;
    cudaGetSymbolAddress((void**)&base, g_buf);
    f16*  H16   = (f16*)(base + OFF_H);
    float* hf   = base + OFF_HF;
    float* hid2 = base + OFF_HID2;
    float* dis1 = base + OFF_DIS1;
    float* dis2 = base + OFF_DIS2;
    int* cc     = (int*)(base + OFF_CC);
    int* sc     = (int*)(base + OFF_SC);
    int* bsn    = (int*)(base + OFF_BSN);
    int* bss    = (int*)(base + OFF_BSS);
    int* coff   = (int*)(base + OFF_COFF);
    int* ccur   = (int*)(base + OFF_CCUR);
    int* soff   = (int*)(base + OFF_SOFF);
    int* scur   = (int*)(base + OFF_SCUR);
    int* csr    = (int*)(base + OFF_CSR);
    int* slist  = (int*)(base + OFF_SLIST);
    bf16* XH = (bf16*)(base + OFF_XH);
    bf16* XL = (bf16*)(base + OFF_XL);
    bf16* YH = (bf16*)(base + OFF_YH);
    bf16* YL = (bf16*)(base + OFF_YL);
    bf16* WH = (bf16*)(base + OFF_WH);
    bf16* WL = (bf16*)(base + OFF_WL);

    cudaFuncSetAttribute(gemm_bf16<1>, cudaFuncAttributeMaxDynamicSharedMemorySize, SMEM_GEMM);
    cudaFuncSetAttribute(gemm_bf16<2>, cudaFuncAttributeMaxDynamicSharedMemorySize, SMEM_GEMM);
    cudaFuncSetAttribute(gemm_bf16<3>, cudaFuncAttributeMaxDynamicSharedMemorySize, SMEM_GEMM);
    cudaFuncSetAttribute(gemm_bf16<4>, cudaFuncAttributeMaxDynamicSharedMemorySize, SMEM_GEMM);
    cudaFuncSetAttribute(gemm_bf16<5>, cudaFuncAttributeMaxDynamicSharedMemorySize, SMEM_GEMM);

    const int T = 256;
    unsigned gy  = (unsigned)((Nn + 127) / 128);
    unsigned gys = (unsigned)((S + 127) / 128);
    dim3 g512(4, gy), g256(2, gy), gh(2, gys);
    unsigned gGat = (unsigned)((Nn + 3) / 4);
    unsigned gPool = (unsigned)((2 * S + 3) / 4);
    int nbN = (2 * Nn + SCAN_B - 1) / SCAN_B;
    int nbS = (2 * S + SCAN_B - 1) / SCAN_B;
    int nz = (int)(OFF_COFF - OFF_CC);
    long t4;

    // ---- prologue ordered so launch #6 (= ncu -s 5 -c 1 capture) is conv GEMM ----
    t4 = (long)Nn * FIN / 4;
    splitA_k<false><<<(unsigned)((t4 + T - 1) / T), T>>>(x, FIN, XH, XL, 512, 0, t4);   // 1
    splitAllW_k<<<(WTOT + T - 1) / T, T>>>(w11, w12, w21, w22, m1w1, m1w2, m2w1, m2w2, mw1, WH, WL); // 2
    zero_k<<<(nz + T - 1) / T, T>>>(base + OFF_CC, nz);                                 // 3
    countall_k<<<(E1 + E2 + Nn + T - 1) / T, T>>>(e1, E1, e2, E2, i1, i2, Nn, S, cc, sc); // 4
    blocksum_k<<<nbN, SCAN_B>>>(cc, bsn, 2 * Nn);                                       // 5
    // ---- layer 1 conv GEMM (launch #6 — profiled) ----
    gemm_bf16<1><<<g512, 256, SMEM_GEMM>>>(XH, XL, 512, WH + WC1, WL + WC1, FIN,
        (float*)H16, nullptr, nullptr, nullptr, 0, 0, Nn, FIN);
    // ---- rest of CSR build (overlaps nothing; GEMM result not needed yet) ----
    blocksum_k<<<nbS, SCAN_B>>>(sc, bss, 2 * S);
    scanbsum_k<<<1, 32>>>(bsn, nbN, coff + 2 * Nn);
    scanbsum_k<<<1, 32>>>(bss, nbS, soff + 2 * S);
    scanblock_k<<<nbN, SCAN_B>>>(cc, bsn, coff, ccur, 2 * Nn);
    scanblock_k<<<nbS, SCAN_B>>>(sc, bss, soff, scur, 2 * S);
    disint_k<<<(Nn + T - 1) / T, T>>>(cc, dis1, dis2, Nn);
    placeboth_k<<<(E1 + E2 + T - 1) / T, T>>>(e1, E1, e2, E2, Nn, ccur, csr);
    placeseg_k<<<(Nn + T - 1) / T, T>>>(i1, i2, Nn, S, scur, slist);

    // ---- layer 1 gathers (single pass each; h fp16 slice L2-resident) ----
    gather_k<<<gGat, T>>>(csr, coff,      dis1, H16,       b11, XH, XL, 0,   Nn);
    gather_k<<<gGat, T>>>(csr, coff + Nn, dis2, H16 + 256, b12, XH, XL, 256, Nn);
    // ---- mlp_1 ----
    gemm_bf16<2><<<g256, 256, SMEM_GEMM>>>(XH, XL, 512, WH + WM1A, WL + WM1A, 512,
        nullptr, m1b1, YH, YL, 256, 0, Nn, 512);
    gemm_bf16<3><<<g256, 256, SMEM_GEMM>>>(YH, YL, 256, WH + WM1B, WL + WM1B, 256,
        nullptr, m1b2, XH, XL, 512, 0, Nn, 256);

    // ---- layer 2 ----
    gemm_bf16<1><<<g512, 256, SMEM_GEMM>>>(XH, XL, 512, WH + WC2, WL + WC2, DD,
        (float*)H16, nullptr, nullptr, nullptr, 0, 0, Nn, DD);
    gather_k<<<gGat, T>>>(csr, coff,      dis1, H16,       b21, XH, XL, 0,   Nn);
    gather_k<<<gGat, T>>>(csr, coff + Nn, dis2, H16 + 256, b22, XH, XL, 256, Nn);
    // ---- mlp_2 ----
    gemm_bf16<2><<<g256, 256, SMEM_GEMM>>>(XH, XL, 512, WH + WM2A, WL + WM2A, 512,
        nullptr, m2b1, YH, YL, 256, 0, Nn, 512);
    gemm_bf16<4><<<g256, 256, SMEM_GEMM>>>(YH, YL, 256, WH + WM2B, WL + WM2B, 256,
        hf, m2b2, nullptr, nullptr, 0, 0, Nn, 256);

    // ---- pooling ----
    poolgather_k<<<gPool, T>>>(slist, soff, hf, XH, XL, S);

    // ---- head ----
    gemm_bf16<5><<<gh, 256, SMEM_GEMM>>>(XH, XL, 512, WH + WHD, WL + WHD, 512,
        hid2, mb1, nullptr, nullptr, 0, 0, S, 512);
    final_k<<<S, DD>>>(hid2, mw2, mb2, out);
}

// round 15
// speedup vs baseline: 1.5149x; 1.2416x over previous
#include <cuda_runtime.h>
#include <cuda_bf16.h>
#include <cuda_fp16.h>
#include <math.h>
#include <stdint.h>
#include <cstdint>

// ---------------- Problem constants ----------------
#define DD 256
#define FIN 128
#define CC 7

typedef __nv_bfloat16 bf16;
typedef __half f16;

// ---------------- Scratch layout (float offsets) ----------------
#define OFF_H     0L             // f16 [M,512] conv GEMM out
#define OFF_HF    51200000L      // fp32 [M,256]
#define OFF_XB    76800000L      // bf16 [M,512] activations (single)
#define OFF_YB    102400000L     // bf16 [M,256]
#define OFF_WH    153600000L     // bf16 weight arena hi (720896)
#define OFF_WL    154000000L
#define OFF_HID2  154400000L
#define OFF_DIS1  155680000L
#define OFF_DIS2  155780000L
// ---- zero block start ----
#define OFF_CC    155880000L     // int[2N]
#define OFF_SC    156080000L     // int[2S]
#define OFF_BSN   156090000L     // int[256]
#define OFF_BSS   156090256L     // int[16]
// ---- zero block end ----
#define OFF_COFF  156090272L     // int[2N+1]
#define OFF_CCUR  156290276L
#define OFF_SOFF  156490276L     // int[2S+1]
#define OFF_SCUR  156500280L
#define OFF_CSR   156510280L     // int[E1+E2]
#define OFF_SLIST 158110280L     // int[2N]
#define SCRATCH_TOTAL 158310280L

// weight arena offsets (bf16 elements)
#define WC1  0
#define WC2  65536
#define WM1A 196608
#define WM1B 327680
#define WM2A 393216
#define WM2B 524288
#define WHD  589824
#define WTOT 720896

__device__ float g_buf[SCRATCH_TOTAL];

// ---------------- helpers ----------------
__device__ __forceinline__ void splitbf(float v, bf16& h, bf16& l) {
    h = __float2bfloat16(v);
    l = __float2bfloat16(v - __bfloat162float(h));
}

__device__ __forceinline__ void ldm_x4(uint32_t r[4], const void* p) {
    uint32_t addr = (uint32_t)__cvta_generic_to_shared(p);
    asm volatile("ldmatrix.sync.aligned.m8n8.x4.shared.b16 {%0,%1,%2,%3}, [%4];"
                 : "=r"(r[0]), "=r"(r[1]), "=r"(r[2]), "=r"(r[3]) : "r"(addr));
}

__device__ __forceinline__ void mma16816(float c[4], const uint32_t a[4],
                                         uint32_t b0, uint32_t b1) {
    asm volatile(
        "mma.sync.aligned.m16n8k16.row.col.f32.bf16.bf16.f32 "
        "{%0,%1,%2,%3}, {%4,%5,%6,%7}, {%8,%9}, {%0,%1,%2,%3};"
        : "+f"(c[0]), "+f"(c[1]), "+f"(c[2]), "+f"(c[3])
        : "r"(a[0]), "r"(a[1]), "r"(a[2]), "r"(a[3]), "r"(b0), "r"(b1));
}

__device__ __forceinline__ void cp16(uint32_t s, const void* g, int sz) {
    asm volatile("cp.async.cg.shared.global [%0], [%1], 16, %2;"
                 :: "r"(s), "l"(g), "r"(sz));
}

// ---------------- prologue kernels ----------------
#define SCAN_B 1024

__global__ void zero_k(float* __restrict__ p, int n) {
    int i = blockIdx.x * blockDim.x + threadIdx.x;
    if (i < n) p[i] = 0.0f;
}

__global__ void countall_k(const int* __restrict__ e1, int E1,
                           const int* __restrict__ e2, int E2,
                           const int* __restrict__ i1, const int* __restrict__ i2,
                           int Nn, int S,
                           int* __restrict__ cc, int* __restrict__ sc) {
    int i = blockIdx.x * blockDim.x + threadIdx.x;
    if (i < E1) atomicAdd(&cc[e1[E1 + i]], 1);
    else if (i < E1 + E2) atomicAdd(&cc[Nn + e2[E2 + (i - E1)]], 1);
    else {
        int j = i - E1 - E2;
        if (j < Nn) {
            atomicAdd(&sc[i1[j]], 1);
            atomicAdd(&sc[S + i2[j]], 1);
        }
    }
}

__global__ void blocksum_k(const int* __restrict__ cnt, int* __restrict__ bsum, int n) {
    int i = blockIdx.x * SCAN_B + threadIdx.x;
    int v = (i < n) ? cnt[i] : 0;
    #pragma unroll
    for (int o = 16; o > 0; o >>= 1) v += __shfl_xor_sync(0xFFFFFFFFu, v, o);
    if ((threadIdx.x & 31) == 0) atomicAdd(&bsum[blockIdx.x], v);
}

__global__ void scanbsum_k(int* __restrict__ bsum, int nb, int* __restrict__ off_n) {
    if (threadIdx.x == 0) {
        int acc = 0;
        for (int i = 0; i < nb; i++) { int v = bsum[i]; bsum[i] = acc; acc += v; }
        *off_n = acc;
    }
}

__global__ void scanblock_k(const int* __restrict__ cnt, const int* __restrict__ bsum,
                            int* __restrict__ off, int* __restrict__ cur, int n) {
    __shared__ int sw[32];
    int tid = threadIdx.x, lane = tid & 31, wid = tid >> 5;
    int i = blockIdx.x * SCAN_B + tid;
    int v = (i < n) ? cnt[i] : 0;
    int inc = v;
    #pragma unroll
    for (int o = 1; o < 32; o <<= 1) {
        int t = __shfl_up_sync(0xFFFFFFFFu, inc, o);
        if (lane >= o) inc += t;
    }
    if (lane == 31) sw[wid] = inc;
    __syncthreads();
    if (wid == 0) {
        int t = sw[lane];
        int ti = t;
        #pragma unroll
        for (int o = 1; o < 32; o <<= 1) {
            int u = __shfl_up_sync(0xFFFFFFFFu, ti, o);
            if (lane >= o) ti += u;
        }
        sw[lane] = ti - t;
    }
    __syncthreads();
    int excl = inc - v + sw[wid] + bsum[blockIdx.x];
    if (i < n) { off[i] = excl; cur[i] = excl; }
}

__global__ void disint_k(const int* __restrict__ cc,
                         float* __restrict__ d1, float* __restrict__ d2, int Nn) {
    int i = blockIdx.x * blockDim.x + threadIdx.x;
    if (i < Nn) {
        d1[i] = rsqrtf((float)cc[i] + 1.0f);
        d2[i] = rsqrtf((float)cc[Nn + i] + 1.0f);
    }
}

__global__ void placeboth_k(const int* __restrict__ e1, int E1,
                            const int* __restrict__ e2, int E2, int Nn,
                            int* __restrict__ cur, int* __restrict__ csr) {
    int i = blockIdx.x * blockDim.x + threadIdx.x;
    if (i < E1) {
        int pos = atomicAdd(&cur[e1[E1 + i]], 1);
        csr[pos] = e1[i];
    } else if (i < E1 + E2) {
        int j = i - E1;
        int pos = atomicAdd(&cur[Nn + e2[E2 + j]], 1);
        csr[pos] = e2[j];
    }
}

__global__ void placeseg_k(const int* __restrict__ i1, const int* __restrict__ i2,
                           int Nn, int S,
                           int* __restrict__ scur, int* __restrict__ slist) {
    int i = blockIdx.x * blockDim.x + threadIdx.x;
    if (i < Nn) {
        int p1 = atomicAdd(&scur[i1[i]], 1);
        slist[p1] = i;
        int p2 = atomicAdd(&scur[S + i2[i]], 1);
        slist[p2] = i;
    }
}

// ---------------- gather conv (h fp16 L2-resident, single bf16 out) ---------
__global__ void gather_k(const int* __restrict__ csr, const int* __restrict__ off,
                         const float* __restrict__ dis,
                         const f16* __restrict__ h,       // pre-offset, stride 512
                         const float* __restrict__ bias,
                         bf16* __restrict__ oB,
                         int ocoff, int Nn) {
    int node = blockIdx.x * 4 + (threadIdx.x >> 6);
    if (node >= Nn) return;
    int c = (threadIdx.x & 63) << 2;
    float di = dis[node];
    float d2 = di * di;
    const __half2* hp = (const __half2*)(h + (size_t)node * 512 + c);
    float2 s0 = __half22float2(hp[0]);
    float2 s1 = __half22float2(hp[1]);
    float4 bv = *(const float4*)(bias + c);
    float4 acc;
    acc.x = bv.x + d2 * s0.x; acc.y = bv.y + d2 * s0.y;
    acc.z = bv.z + d2 * s1.x; acc.w = bv.w + d2 * s1.y;
    int s = off[node], e = off[node + 1];
    for (int k = s; k < e; k++) {
        int j = csr[k];
        float coef = di * dis[j];
        const __half2* hj = (const __half2*)(h + (size_t)j * 512 + c);
        float2 f0 = __half22float2(hj[0]);
        float2 f1 = __half22float2(hj[1]);
        acc.x += coef * f0.x; acc.y += coef * f0.y;
        acc.z += coef * f1.x; acc.w += coef * f1.y;
    }
    acc.x = fmaxf(acc.x, 0.f); acc.y = fmaxf(acc.y, 0.f);
    acc.z = fmaxf(acc.z, 0.f); acc.w = fmaxf(acc.w, 0.f);
    size_t o = (size_t)node * 512 + ocoff + c;
    __nv_bfloat162 t0, t1;
    t0.x = __float2bfloat16(acc.x); t0.y = __float2bfloat16(acc.y);
    t1.x = __float2bfloat16(acc.z); t1.y = __float2bfloat16(acc.w);
    *(__nv_bfloat162*)(oB + o) = t0;
    *(__nv_bfloat162*)(oB + o + 2) = t1;
}

// ---------------- pool gather ----------------
__global__ void poolgather_k(const int* __restrict__ slist, const int* __restrict__ soff,
                             const float* __restrict__ hf,
                             bf16* __restrict__ oB, int S) {
    int g = blockIdx.x * 4 + (threadIdx.x >> 6);
    if (g >= 2 * S) return;
    int part = (g >= S);
    int seg = g - part * S;
    int c = (threadIdx.x & 63) << 2;
    int s = soff[g], e = soff[g + 1];
    float4 acc = make_float4(0.f, 0.f, 0.f, 0.f);
    for (int k = s; k < e; k++) {
        int node = slist[k];
        float4 hv = *(const float4*)(hf + (size_t)node * 256 + c);
        acc.x += hv.x; acc.y += hv.y; acc.z += hv.z; acc.w += hv.w;
    }
    float inv = 1.0f / fmaxf((float)(e - s), 1.0f);
    acc.x *= inv; acc.y *= inv; acc.z *= inv; acc.w *= inv;
    size_t o = (size_t)seg * 512 + part * 256 + c;
    __nv_bfloat162 t0, t1;
    t0.x = __float2bfloat16(acc.x); t0.y = __float2bfloat16(acc.y);
    t1.x = __float2bfloat16(acc.z); t1.y = __float2bfloat16(acc.w);
    *(__nv_bfloat162*)(oB + o) = t0;
    *(__nv_bfloat162*)(oB + o + 2) = t1;
}

// ---------------- casts/splits ----------------
__global__ void castA_k(const float* __restrict__ src, int Ks,
                        bf16* __restrict__ dB, int dstride, int coff, long total4) {
    long gid = blockIdx.x * (long)blockDim.x + threadIdx.x;
    if (gid >= total4) return;
    long e = gid * 4;
    long r = e / Ks;
    int  c = (int)(e - r * Ks);
    float4 v = *(const float4*)(src + e);
    __nv_bfloat162 t0, t1;
    t0.x = __float2bfloat16(v.x); t0.y = __float2bfloat16(v.y);
    t1.x = __float2bfloat16(v.z); t1.y = __float2bfloat16(v.w);
    __nv_bfloat162* p = (__nv_bfloat162*)(dB + r * (long)dstride + coff + c);
    p[0] = t0; p[1] = t1;
}

__global__ void splitAllW_k(const float* __restrict__ w11, const float* __restrict__ w12,
                            const float* __restrict__ w21, const float* __restrict__ w22,
                            const float* __restrict__ m1w1, const float* __restrict__ m1w2,
                            const float* __restrict__ m2w1, const float* __restrict__ m2w2,
                            const float* __restrict__ mw1,
                            bf16* __restrict__ dh, bf16* __restrict__ dl) {
    int gid = blockIdx.x * blockDim.x + threadIdx.x;
    if (gid >= WTOT) return;
    float v; int dst;
    if (gid < 65536) {
        int l = gid, which = l >= 32768, g = l - which * 32768;
        int k = g >> 8, n = g & 255;
        v = which ? w12[g] : w11[g];
        dst = WC1 + (n + which * 256) * 128 + k;
    } else if (gid < 196608) {
        int l = gid - 65536, which = l >= 65536, g = l - which * 65536;
        int k = g >> 8, n = g & 255;
        v = which ? w22[g] : w21[g];
        dst = WC2 + (n + which * 256) * 256 + k;
    } else if (gid < 327680) {
        int g = gid - 196608;
        int k = g >> 8, n = g & 255;
        v = m1w1[g];
        dst = WM1A + n * 512 + k;
    } else if (gid < 393216) {
        int g = gid - 327680;
        int k = g >> 8, n = g & 255;
        v = m1w2[g];
        dst = WM1B + n * 256 + k;
    } else if (gid < 524288) {
        int g = gid - 393216;
        int k = g >> 8, n = g & 255;
        v = m2w1[g];
        dst = WM2A + n * 512 + k;
    } else if (gid < 589824) {
        int g = gid - 524288;
        int k = g >> 8, n = g & 255;
        v = m2w2[g];
        dst = WM2B + n * 256 + k;
    } else {
        int g = gid - 589824;
        int k = g >> 8, n = g & 255;
        v = mw1[g];
        dst = WHD + n * 512 + k;
    }
    bf16 h, l;
    splitbf(v, h, l);
    dh[dst] = h;
    dl[dst] = l;
}

// ---------------- head ----------------
__global__ void final_k(const float* __restrict__ hid, const float* __restrict__ w2,
                        const float* __restrict__ b2, float* __restrict__ out) {
    __shared__ float sh[DD];
    __shared__ float lg[CC];
    int s = blockIdx.x;
    int tid = threadIdx.x;
    sh[tid] = hid[(size_t)s * DD + tid];
    __syncthreads();
    int w = tid >> 5, lane = tid & 31;
    if (w < CC) {
        float sum = 0.0f;
        for (int k = lane; k < DD; k += 32) sum += sh[k] * w2[k * CC + w];
        #pragma unroll
        for (int o = 16; o > 0; o >>= 1) sum += __shfl_xor_sync(0xFFFFFFFFu, sum, o);
        if (lane == 0) lg[w] = sum + b2[w];
    }
    __syncthreads();
    if (tid == 0) {
        float mx = -1e30f;
        #pragma unroll
        for (int c = 0; c < CC; c++) mx = fmaxf(mx, lg[c]);
        float se = 0.0f;
        #pragma unroll
        for (int c = 0; c < CC; c++) se += expf(lg[c] - mx);
        float lse = mx + logf(se);
        #pragma unroll
        for (int c = 0; c < CC; c++) out[(size_t)s * CC + c] = lg[c] - lse;
    }
}

// ---------------- bf16 2-term double-buffered GEMM ----------------
// C = A(bf16) @ (Wh + Wl)^T, fp32 accum.
// EPI=1 RAW_F16: ((f16*)C)[r*512+c]=f16(acc)
// EPI=2 bf16(relu(acc+b))->oB   EPI=3 bf16(acc+b)->oB
// EPI=4 C[r*256+c]=acc+b        EPI=5 relu variant
#define LDK2 40
#define STAGE_BYTES 30720   // A 10240 | Bh 10240 | Bl 10240

__device__ __forceinline__ void gemm_prefetch(
    char* smbase, int stage, int row, int hlf,
    const bf16* A, int lda,
    const bf16* BH, const bf16* BL, int ldb,
    int bm, int bn, int M, int k0)
{
    int gra = bm + row;
    int szA = (gra < M) ? 16 : 0;
    if (gra >= M) gra = 0;
    const char* pA  = (const char*)(A + (size_t)gra * lda + k0) + hlf * 32;
    int grb = bn + row;
    const char* pBH = (const char*)(BH + (size_t)grb * ldb + k0) + hlf * 32;
    const char* pBL = (const char*)(BL + (size_t)grb * ldb + k0) + hlf * 32;
    uint32_t so = (uint32_t)__cvta_generic_to_shared(smbase + stage * STAGE_BYTES)
                  + row * (LDK2 * 2) + hlf * 32;
    cp16(so,              pA,       szA);  cp16(so + 16,          pA + 16,  szA);
    cp16(so + 10240,      pBH,      16);   cp16(so + 10240 + 16,  pBH + 16, 16);
    cp16(so + 20480,      pBL,      16);   cp16(so + 20480 + 16,  pBL + 16, 16);
}

template<int EPI>
__global__ void __launch_bounds__(256)
gemm_bf16(const bf16* __restrict__ A, int lda,
          const bf16* __restrict__ BH, const bf16* __restrict__ BL, int ldb,
          float* __restrict__ C,
          const float* __restrict__ bias,
          bf16* __restrict__ oB, int ostride, int ocoff,
          int M, int K)
{
    extern __shared__ char sm_[];
    int tid = threadIdx.x, wid = tid >> 5, lane = tid & 31;
    int bm = blockIdx.y * 128, bn = blockIdx.x * 128;
    int wm = (wid & 3) * 32, wn = (wid >> 2) * 64;
    int idx = lane >> 3, lr = lane & 7;
    int row = tid >> 1, hlf = tid & 1;

    float acc[2][8][4];
    #pragma unroll
    for (int i = 0; i < 2; i++)
        #pragma unroll
        for (int j = 0; j < 8; j++)
            #pragma unroll
            for (int q = 0; q < 4; q++) acc[i][j][q] = 0.0f;

    int KT = K >> 5;
    gemm_prefetch(sm_, 0, row, hlf, A, lda, BH, BL, ldb, bm, bn, M, 0);
    asm volatile("cp.async.commit_group;");

    for (int kt = 0; kt < KT; kt++) {
        int s = kt & 1;
        if (kt + 1 < KT) {
            gemm_prefetch(sm_, s ^ 1, row, hlf, A, lda, BH, BL, ldb,
                          bm, bn, M, (kt + 1) << 5);
            asm volatile("cp.async.commit_group;");
            asm volatile("cp.async.wait_group 1;");
        } else {
            asm volatile("cp.async.wait_group 0;");
        }
        __syncthreads();

        const bf16* sA  = (const bf16*)(sm_ + s * STAGE_BYTES);
        const bf16* sBh = (const bf16*)(sm_ + s * STAGE_BYTES + 10240);
        const bf16* sBl = (const bf16*)(sm_ + s * STAGE_BYTES + 20480);

        #pragma unroll
        for (int ks = 0; ks < 2; ks++) {
            int kb = ks * 16;
            uint32_t a[2][4];
            #pragma unroll
            for (int mf = 0; mf < 2; mf++) {
                int rr = wm + mf * 16 + (idx & 1) * 8 + lr;
                int cc2 = kb + (idx >> 1) * 8;
                ldm_x4(a[mf], &sA[rr * LDK2 + cc2]);
            }
            uint32_t bh[4][4], bl[4][4];
            #pragma unroll
            for (int bg = 0; bg < 4; bg++) {
                int rr = wn + bg * 16 + (idx >> 1) * 8 + lr;
                int cc2 = kb + (idx & 1) * 8;
                ldm_x4(bh[bg], &sBh[rr * LDK2 + cc2]);
                ldm_x4(bl[bg], &sBl[rr * LDK2 + cc2]);
            }
            #pragma unroll
            for (int mf = 0; mf < 2; mf++)
                #pragma unroll
                for (int ng = 0; ng < 8; ng++) {
                    int bg = ng >> 1, pr = (ng & 1) * 2;
                    mma16816(acc[mf][ng], a[mf], bh[bg][pr], bh[bg][pr + 1]);
                    mma16816(acc[mf][ng], a[mf], bl[bg][pr], bl[bg][pr + 1]);
                }
        }
        __syncthreads();
    }

    // ---- epilogue ----
    int r0 = bm + wm + (lane >> 2);
    int lc0 = wn + (lane & 3) * 2;
    #pragma unroll
    for (int mf = 0; mf < 2; mf++) {
        #pragma unroll
        for (int hf2 = 0; hf2 < 2; hf2++) {
            int r = r0 + mf * 16 + hf2 * 8;
            if (r >= M) continue;
            #pragma unroll
            for (int ng = 0; ng < 8; ng++) {
                int lc = lc0 + ng * 8;
                int c = bn + lc;
                float v0 = acc[mf][ng][hf2 * 2 + 0];
                float v1 = acc[mf][ng][hf2 * 2 + 1];
                if (EPI == 1) {
                    __half2 t;
                    t.x = __float2half_rn(v0); t.y = __float2half_rn(v1);
                    *(__half2*)((f16*)C + (size_t)r * 512 + c) = t;
                } else if (EPI == 2 || EPI == 3) {
                    v0 += bias[c]; v1 += bias[c + 1];
                    if (EPI == 2) { v0 = fmaxf(v0, 0.f); v1 = fmaxf(v1, 0.f); }
                    __nv_bfloat162 t;
                    t.x = __float2bfloat16(v0); t.y = __float2bfloat16(v1);
                    *(__nv_bfloat162*)(oB + (size_t)r * ostride + ocoff + c) = t;
                } else {
                    v0 += bias[c]; v1 += bias[c + 1];
                    if (EPI == 5) { v0 = fmaxf(v0, 0.f); v1 = fmaxf(v1, 0.f); }
                    float2 st; st.x = v0; st.y = v1;
                    *(float2*)(C + (size_t)r * 256 + c) = st;
                }
            }
        }
    }
}

// ---------------- launch ----------------
#define SMEM_GEMM (2 * STAGE_BYTES)

extern "C" void kernel_launch(void* const* d_in, const int* in_sizes, int n_in,
                              void* d_out, int out_size) {
    const float* x    = (const float*)d_in[0];
    const int*   e1   = (const int*)d_in[1];
    const int*   e2   = (const int*)d_in[2];
    const int*   i1   = (const int*)d_in[3];
    const int*   i2   = (const int*)d_in[4];
    const float* w11  = (const float*)d_in[5];
    const float* b11  = (const float*)d_in[6];
    const float* w12  = (const float*)d_in[7];
    const float* b12  = (const float*)d_in[8];
    const float* w21  = (const float*)d_in[9];
    const float* b21  = (const float*)d_in[10];
    const float* w22  = (const float*)d_in[11];
    const float* b22  = (const float*)d_in[12];
    const float* m1w1 = (const float*)d_in[13];
    const float* m1b1 = (const float*)d_in[14];
    const float* m1w2 = (const float*)d_in[15];
    const float* m1b2 = (const float*)d_in[16];
    const float* m2w1 = (const float*)d_in[17];
    const float* m2b1 = (const float*)d_in[18];
    const float* m2w2 = (const float*)d_in[19];
    const float* m2b2 = (const float*)d_in[20];
    const float* mw1  = (const float*)d_in[21];
    const float* mb1  = (const float*)d_in[22];
    const float* mw2  = (const float*)d_in[23];
    const float* mb2  = (const float*)d_in[24];
    float* out = (float*)d_out;

    int Nn = in_sizes[0] / FIN;
    int E1 = in_sizes[1] / 2;
    int E2 = in_sizes[2] / 2;
    int S  = out_size / CC;

    float* base = nullptr;
    cudaGetSymbolAddress((void**)&base, g_buf);
    f16*  H16   = (f16*)(base + OFF_H);
    float* hf   = base + OFF_HF;
    float* hid2 = base + OFF_HID2;
    float* dis1 = base + OFF_DIS1;
    float* dis2 = base + OFF_DIS2;
    int* cc     = (int*)(base + OFF_CC);
    int* sc     = (int*)(base + OFF_SC);
    int* bsn    = (int*)(base + OFF_BSN);
    int* bss    = (int*)(base + OFF_BSS);
    int* coff   = (int*)(base + OFF_COFF);
    int* ccur   = (int*)(base + OFF_CCUR);
    int* soff   = (int*)(base + OFF_SOFF);
    int* scur   = (int*)(base + OFF_SCUR);
    int* csr    = (int*)(base + OFF_CSR);
    int* slist  = (int*)(base + OFF_SLIST);
    bf16* XB = (bf16*)(base + OFF_XB);
    bf16* YB = (bf16*)(base + OFF_YB);
    bf16* WH = (bf16*)(base + OFF_WH);
    bf16* WL = (bf16*)(base + OFF_WL);

    cudaFuncSetAttribute(gemm_bf16<1>, cudaFuncAttributeMaxDynamicSharedMemorySize, SMEM_GEMM);
    cudaFuncSetAttribute(gemm_bf16<2>, cudaFuncAttributeMaxDynamicSharedMemorySize, SMEM_GEMM);
    cudaFuncSetAttribute(gemm_bf16<3>, cudaFuncAttributeMaxDynamicSharedMemorySize, SMEM_GEMM);
    cudaFuncSetAttribute(gemm_bf16<4>, cudaFuncAttributeMaxDynamicSharedMemorySize, SMEM_GEMM);
    cudaFuncSetAttribute(gemm_bf16<5>, cudaFuncAttributeMaxDynamicSharedMemorySize, SMEM_GEMM);

    const int T = 256;
    unsigned gy  = (unsigned)((Nn + 127) / 128);
    unsigned gys = (unsigned)((S + 127) / 128);
    dim3 g512(4, gy), g256(2, gy), gh(2, gys);
    unsigned gGat = (unsigned)((Nn + 3) / 4);
    unsigned gPool = (unsigned)((2 * S + 3) / 4);
    int nbN = (2 * Nn + SCAN_B - 1) / SCAN_B;
    int nbS = (2 * S + SCAN_B - 1) / SCAN_B;
    int nz = (int)(OFF_COFF - OFF_CC);
    long t4;

    // ---- prologue ordered so launch #6 (= ncu -s 5 -c 1 capture) is conv GEMM ----
    t4 = (long)Nn * FIN / 4;
    castA_k<<<(unsigned)((t4 + T - 1) / T), T>>>(x, FIN, XB, 512, 0, t4);               // 1
    splitAllW_k<<<(WTOT + T - 1) / T, T>>>(w11, w12, w21, w22, m1w1, m1w2, m2w1, m2w2, mw1, WH, WL); // 2
    zero_k<<<(nz + T - 1) / T, T>>>(base + OFF_CC, nz);                                 // 3
    countall_k<<<(E1 + E2 + Nn + T - 1) / T, T>>>(e1, E1, e2, E2, i1, i2, Nn, S, cc, sc); // 4
    blocksum_k<<<nbN, SCAN_B>>>(cc, bsn, 2 * Nn);                                       // 5
    // ---- layer 1 conv GEMM (launch #6 — profiled) ----
    gemm_bf16<1><<<g512, 256, SMEM_GEMM>>>(XB, 512, WH + WC1, WL + WC1, FIN,
        (float*)H16, nullptr, nullptr, 0, 0, Nn, FIN);
    // ---- rest of CSR build ----
    blocksum_k<<<nbS, SCAN_B>>>(sc, bss, 2 * S);
    scanbsum_k<<<1, 32>>>(bsn, nbN, coff + 2 * Nn);
    scanbsum_k<<<1, 32>>>(bss, nbS, soff + 2 * S);
    scanblock_k<<<nbN, SCAN_B>>>(cc, bsn, coff, ccur, 2 * Nn);
    scanblock_k<<<nbS, SCAN_B>>>(sc, bss, soff, scur, 2 * S);
    disint_k<<<(Nn + T - 1) / T, T>>>(cc, dis1, dis2, Nn);
    placeboth_k<<<(E1 + E2 + T - 1) / T, T>>>(e1, E1, e2, E2, Nn, ccur, csr);
    placeseg_k<<<(Nn + T - 1) / T, T>>>(i1, i2, Nn, S, scur, slist);

    // ---- layer 1 gathers ----
    gather_k<<<gGat, T>>>(csr, coff,      dis1, H16,       b11, XB, 0,   Nn);
    gather_k<<<gGat, T>>>(csr, coff + Nn, dis2, H16 + 256, b12, XB, 256, Nn);
    // ---- mlp_1 ----
    gemm_bf16<2><<<g256, 256, SMEM_GEMM>>>(XB, 512, WH + WM1A, WL + WM1A, 512,
        nullptr, m1b1, YB, 256, 0, Nn, 512);
    gemm_bf16<3><<<g256, 256, SMEM_GEMM>>>(YB, 256, WH + WM1B, WL + WM1B, 256,
        nullptr, m1b2, XB, 512, 0, Nn, 256);

    // ---- layer 2 ----
    gemm_bf16<1><<<g512, 256, SMEM_GEMM>>>(XB, 512, WH + WC2, WL + WC2, DD,
        (float*)H16, nullptr, nullptr, 0, 0, Nn, DD);
    gather_k<<<gGat, T>>>(csr, coff,      dis1, H16,       b21, XB, 0,   Nn);
    gather_k<<<gGat, T>>>(csr, coff + Nn, dis2, H16 + 256, b22, XB, 256, Nn);
    // ---- mlp_2 ----
    gemm_bf16<2><<<g256, 256, SMEM_GEMM>>>(XB, 512, WH + WM2A, WL + WM2A, 512,
        nullptr, m2b1, YB, 256, 0, Nn, 512);
    gemm_bf16<4><<<g256, 256, SMEM_GEMM>>>(YB, 256, WH + WM2B, WL + WM2B, 256,
        hf, m2b2, nullptr, 0, 0, Nn, 256);

    // ---- pooling ----
    poolgather_k<<<gPool, T>>>(slist, soff, hf, XB, S);

    // ---- head ----
    gemm_bf16<5><<<gh, 256, SMEM_GEMM>>>(XB, 512, WH + WHD, WL + WHD, 512,
        hid2, mb1, nullptr, 0, 0, S, 512);
    final_k<<<S, DD>>>(hid2, mw2, mb2, out);
}

// round 16
// speedup vs baseline: 1.9899x; 1.3135x over previous
#include <cuda_runtime.h>
#include <cuda_bf16.h>
#include <cuda_fp16.h>
#include <math.h>
#include <stdint.h>
#include <cstdint>

// ---------------- Problem constants ----------------
#define DD 256
#define FIN 128
#define CC 7

typedef __nv_bfloat16 bf16;
typedef __half f16;

// ---------------- Scratch layout (float offsets) ----------------
#define OFF_H     0L             // f16 [M,512] conv GEMM out
#define OFF_HF    51200000L      // fp32 [M,256]
#define OFF_XB    76800000L      // bf16 [M,512] activations (single)
#define OFF_YB    102400000L     // bf16 [M,256]
#define OFF_WB    153600000L     // bf16 weight arena (720896)
#define OFF_HID2  154400000L
#define OFF_DIS1  155680000L
#define OFF_DIS2  155780000L
// ---- zero block start ----
#define OFF_CC    155880000L     // int[2N]
#define OFF_SC    156080000L     // int[2S]
#define OFF_BSN   156090000L     // int[256]
#define OFF_BSS   156090256L     // int[16]
// ---- zero block end ----
#define OFF_COFF  156090272L     // int[2N+1]
#define OFF_CCUR  156290276L
#define OFF_SOFF  156490276L     // int[2S+1]
#define OFF_SCUR  156500280L
#define OFF_CSR   156510280L     // int[E1+E2]
#define OFF_SLIST 158110280L     // int[2N]
#define SCRATCH_TOTAL 158310280L

// weight arena offsets (bf16 elements)
#define WC1  0
#define WC2  65536
#define WM1A 196608
#define WM1B 327680
#define WM2A 393216
#define WM2B 524288
#define WHD  589824
#define WTOT 720896

__device__ float g_buf[SCRATCH_TOTAL];

// ---------------- helpers ----------------
__device__ __forceinline__ void ldm_x4(uint32_t r[4], const void* p) {
    uint32_t addr = (uint32_t)__cvta_generic_to_shared(p);
    asm volatile("ldmatrix.sync.aligned.m8n8.x4.shared.b16 {%0,%1,%2,%3}, [%4];"
                 : "=r"(r[0]), "=r"(r[1]), "=r"(r[2]), "=r"(r[3]) : "r"(addr));
}

__device__ __forceinline__ void mma16816(float c[4], const uint32_t a[4],
                                         uint32_t b0, uint32_t b1) {
    asm volatile(
        "mma.sync.aligned.m16n8k16.row.col.f32.bf16.bf16.f32 "
        "{%0,%1,%2,%3}, {%4,%5,%6,%7}, {%8,%9}, {%0,%1,%2,%3};"
        : "+f"(c[0]), "+f"(c[1]), "+f"(c[2]), "+f"(c[3])
        : "r"(a[0]), "r"(a[1]), "r"(a[2]), "r"(a[3]), "r"(b0), "r"(b1));
}

__device__ __forceinline__ void cp16(uint32_t s, const void* g, int sz) {
    asm volatile("cp.async.cg.shared.global [%0], [%1], 16, %2;"
                 :: "r"(s), "l"(g), "r"(sz));
}

// ---------------- prologue kernels ----------------
#define SCAN_B 1024

__global__ void zero_k(float* __restrict__ p, int n) {
    int i = blockIdx.x * blockDim.x + threadIdx.x;
    if (i < n) p[i] = 0.0f;
}

__global__ void countall_k(const int* __restrict__ e1, int E1,
                           const int* __restrict__ e2, int E2,
                           const int* __restrict__ i1, const int* __restrict__ i2,
                           int Nn, int S,
                           int* __restrict__ cc, int* __restrict__ sc) {
    int i = blockIdx.x * blockDim.x + threadIdx.x;
    if (i < E1) atomicAdd(&cc[e1[E1 + i]], 1);
    else if (i < E1 + E2) atomicAdd(&cc[Nn + e2[E2 + (i - E1)]], 1);
    else {
        int j = i - E1 - E2;
        if (j < Nn) {
            atomicAdd(&sc[i1[j]], 1);
            atomicAdd(&sc[S + i2[j]], 1);
        }
    }
}

__global__ void blocksum_k(const int* __restrict__ cnt, int* __restrict__ bsum, int n) {
    int i = blockIdx.x * SCAN_B + threadIdx.x;
    int v = (i < n) ? cnt[i] : 0;
    #pragma unroll
    for (int o = 16; o > 0; o >>= 1) v += __shfl_xor_sync(0xFFFFFFFFu, v, o);
    if ((threadIdx.x & 31) == 0) atomicAdd(&bsum[blockIdx.x], v);
}

__global__ void scanbsum_k(int* __restrict__ bsum, int nb, int* __restrict__ off_n) {
    if (threadIdx.x == 0) {
        int acc = 0;
        for (int i = 0; i < nb; i++) { int v = bsum[i]; bsum[i] = acc; acc += v; }
        *off_n = acc;
    }
}

__global__ void scanblock_k(const int* __restrict__ cnt, const int* __restrict__ bsum,
                            int* __restrict__ off, int* __restrict__ cur, int n) {
    __shared__ int sw[32];
    int tid = threadIdx.x, lane = tid & 31, wid = tid >> 5;
    int i = blockIdx.x * SCAN_B + tid;
    int v = (i < n) ? cnt[i] : 0;
    int inc = v;
    #pragma unroll
    for (int o = 1; o < 32; o <<= 1) {
        int t = __shfl_up_sync(0xFFFFFFFFu, inc, o);
        if (lane >= o) inc += t;
    }
    if (lane == 31) sw[wid] = inc;
    __syncthreads();
    if (wid == 0) {
        int t = sw[lane];
        int ti = t;
        #pragma unroll
        for (int o = 1; o < 32; o <<= 1) {
            int u = __shfl_up_sync(0xFFFFFFFFu, ti, o);
            if (lane >= o) ti += u;
        }
        sw[lane] = ti - t;
    }
    __syncthreads();
    int excl = inc - v + sw[wid] + bsum[blockIdx.x];
    if (i < n) { off[i] = excl; cur[i] = excl; }
}

__global__ void disint_k(const int* __restrict__ cc,
                         float* __restrict__ d1, float* __restrict__ d2, int Nn) {
    int i = blockIdx.x * blockDim.x + threadIdx.x;
    if (i < Nn) {
        d1[i] = rsqrtf((float)cc[i] + 1.0f);
        d2[i] = rsqrtf((float)cc[Nn + i] + 1.0f);
    }
}

__global__ void placeboth_k(const int* __restrict__ e1, int E1,
                            const int* __restrict__ e2, int E2, int Nn,
                            int* __restrict__ cur, int* __restrict__ csr) {
    int i = blockIdx.x * blockDim.x + threadIdx.x;
    if (i < E1) {
        int pos = atomicAdd(&cur[e1[E1 + i]], 1);
        csr[pos] = e1[i];
    } else if (i < E1 + E2) {
        int j = i - E1;
        int pos = atomicAdd(&cur[Nn + e2[E2 + j]], 1);
        csr[pos] = e2[j];
    }
}

__global__ void placeseg_k(const int* __restrict__ i1, const int* __restrict__ i2,
                           int Nn, int S,
                           int* __restrict__ scur, int* __restrict__ slist) {
    int i = blockIdx.x * blockDim.x + threadIdx.x;
    if (i < Nn) {
        int p1 = atomicAdd(&scur[i1[i]], 1);
        slist[p1] = i;
        int p2 = atomicAdd(&scur[S + i2[i]], 1);
        slist[p2] = i;
    }
}

// ---------------- gather conv (h fp16 L2-resident, single bf16 out) ---------
__global__ void gather_k(const int* __restrict__ csr, const int* __restrict__ off,
                         const float* __restrict__ dis,
                         const f16* __restrict__ h,       // pre-offset, stride 512
                         const float* __restrict__ bias,
                         bf16* __restrict__ oB,
                         int ocoff, int Nn) {
    int node = blockIdx.x * 4 + (threadIdx.x >> 6);
    if (node >= Nn) return;
    int c = (threadIdx.x & 63) << 2;
    float di = dis[node];
    float d2 = di * di;
    const __half2* hp = (const __half2*)(h + (size_t)node * 512 + c);
    float2 s0 = __half22float2(hp[0]);
    float2 s1 = __half22float2(hp[1]);
    float4 bv = *(const float4*)(bias + c);
    float4 acc;
    acc.x = bv.x + d2 * s0.x; acc.y = bv.y + d2 * s0.y;
    acc.z = bv.z + d2 * s1.x; acc.w = bv.w + d2 * s1.y;
    int s = off[node], e = off[node + 1];
    for (int k = s; k < e; k++) {
        int j = csr[k];
        float coef = di * dis[j];
        const __half2* hj = (const __half2*)(h + (size_t)j * 512 + c);
        float2 f0 = __half22float2(hj[0]);
        float2 f1 = __half22float2(hj[1]);
        acc.x += coef * f0.x; acc.y += coef * f0.y;
        acc.z += coef * f1.x; acc.w += coef * f1.y;
    }
    acc.x = fmaxf(acc.x, 0.f); acc.y = fmaxf(acc.y, 0.f);
    acc.z = fmaxf(acc.z, 0.f); acc.w = fmaxf(acc.w, 0.f);
    size_t o = (size_t)node * 512 + ocoff + c;
    __nv_bfloat162 t0, t1;
    t0.x = __float2bfloat16(acc.x); t0.y = __float2bfloat16(acc.y);
    t1.x = __float2bfloat16(acc.z); t1.y = __float2bfloat16(acc.w);
    *(__nv_bfloat162*)(oB + o) = t0;
    *(__nv_bfloat162*)(oB + o + 2) = t1;
}

// ---------------- pool gather ----------------
__global__ void poolgather_k(const int* __restrict__ slist, const int* __restrict__ soff,
                             const float* __restrict__ hf,
                             bf16* __restrict__ oB, int S) {
    int g = blockIdx.x * 4 + (threadIdx.x >> 6);
    if (g >= 2 * S) return;
    int part = (g >= S);
    int seg = g - part * S;
    int c = (threadIdx.x & 63) << 2;
    int s = soff[g], e = soff[g + 1];
    float4 acc = make_float4(0.f, 0.f, 0.f, 0.f);
    for (int k = s; k < e; k++) {
        int node = slist[k];
        float4 hv = *(const float4*)(hf + (size_t)node * 256 + c);
        acc.x += hv.x; acc.y += hv.y; acc.z += hv.z; acc.w += hv.w;
    }
    float inv = 1.0f / fmaxf((float)(e - s), 1.0f);
    acc.x *= inv; acc.y *= inv; acc.z *= inv; acc.w *= inv;
    size_t o = (size_t)seg * 512 + part * 256 + c;
    __nv_bfloat162 t0, t1;
    t0.x = __float2bfloat16(acc.x); t0.y = __float2bfloat16(acc.y);
    t1.x = __float2bfloat16(acc.z); t1.y = __float2bfloat16(acc.w);
    *(__nv_bfloat162*)(oB + o) = t0;
    *(__nv_bfloat162*)(oB + o + 2) = t1;
}

// ---------------- casts ----------------
__global__ void castA_k(const float* __restrict__ src, int Ks,
                        bf16* __restrict__ dB, int dstride, int coff, long total4) {
    long gid = blockIdx.x * (long)blockDim.x + threadIdx.x;
    if (gid >= total4) return;
    long e = gid * 4;
    long r = e / Ks;
    int  c = (int)(e - r * Ks);
    float4 v = *(const float4*)(src + e);
    __nv_bfloat162 t0, t1;
    t0.x = __float2bfloat16(v.x); t0.y = __float2bfloat16(v.y);
    t1.x = __float2bfloat16(v.z); t1.y = __float2bfloat16(v.w);
    __nv_bfloat162* p = (__nv_bfloat162*)(dB + r * (long)dstride + coff + c);
    p[0] = t0; p[1] = t1;
}

// all 9 weight matrices -> transposed bf16 arena (single rounding)
__global__ void castAllW_k(const float* __restrict__ w11, const float* __restrict__ w12,
                           const float* __restrict__ w21, const float* __restrict__ w22,
                           const float* __restrict__ m1w1, const float* __restrict__ m1w2,
                           const float* __restrict__ m2w1, const float* __restrict__ m2w2,
                           const float* __restrict__ mw1,
                           bf16* __restrict__ dB) {
    int gid = blockIdx.x * blockDim.x + threadIdx.x;
    if (gid >= WTOT) return;
    float v; int dst;
    if (gid < 65536) {
        int l = gid, which = l >= 32768, g = l - which * 32768;
        int k = g >> 8, n = g & 255;
        v = which ? w12[g] : w11[g];
        dst = WC1 + (n + which * 256) * 128 + k;
    } else if (gid < 196608) {
        int l = gid - 65536, which = l >= 65536, g = l - which * 65536;
        int k = g >> 8, n = g & 255;
        v = which ? w22[g] : w21[g];
        dst = WC2 + (n + which * 256) * 256 + k;
    } else if (gid < 327680) {
        int g = gid - 196608;
        int k = g >> 8, n = g & 255;
        v = m1w1[g];
        dst = WM1A + n * 512 + k;
    } else if (gid < 393216) {
        int g = gid - 327680;
        int k = g >> 8, n = g & 255;
        v = m1w2[g];
        dst = WM1B + n * 256 + k;
    } else if (gid < 524288) {
        int g = gid - 393216;
        int k = g >> 8, n = g & 255;
        v = m2w1[g];
        dst = WM2A + n * 512 + k;
    } else if (gid < 589824) {
        int g = gid - 524288;
        int k = g >> 8, n = g & 255;
        v = m2w2[g];
        dst = WM2B + n * 256 + k;
    } else {
        int g = gid - 589824;
        int k = g >> 8, n = g & 255;
        v = mw1[g];
        dst = WHD + n * 512 + k;
    }
    dB[dst] = __float2bfloat16(v);
}

// ---------------- head ----------------
__global__ void final_k(const float* __restrict__ hid, const float* __restrict__ w2,
                        const float* __restrict__ b2, float* __restrict__ out) {
    __shared__ float sh[DD];
    __shared__ float lg[CC];
    int s = blockIdx.x;
    int tid = threadIdx.x;
    sh[tid] = hid[(size_t)s * DD + tid];
    __syncthreads();
    int w = tid >> 5, lane = tid & 31;
    if (w < CC) {
        float sum = 0.0f;
        for (int k = lane; k < DD; k += 32) sum += sh[k] * w2[k * CC + w];
        #pragma unroll
        for (int o = 16; o > 0; o >>= 1) sum += __shfl_xor_sync(0xFFFFFFFFu, sum, o);
        if (lane == 0) lg[w] = sum + b2[w];
    }
    __syncthreads();
    if (tid == 0) {
        float mx = -1e30f;
        #pragma unroll
        for (int c = 0; c < CC; c++) mx = fmaxf(mx, lg[c]);
        float se = 0.0f;
        #pragma unroll
        for (int c = 0; c < CC; c++) se += expf(lg[c] - mx);
        float lse = mx + logf(se);
        #pragma unroll
        for (int c = 0; c < CC; c++) out[(size_t)s * CC + c] = lg[c] - lse;
    }
}

// ---------------- plain bf16 double-buffered GEMM ----------------
// C = A(bf16) @ W(bf16)^T, fp32 accum.
// EPI=1 RAW_F16: ((f16*)C)[r*512+c]=f16(acc)
// EPI=2 bf16(relu(acc+b))->oB   EPI=3 bf16(acc+b)->oB
// EPI=4 C[r*256+c]=acc+b        EPI=5 relu variant
#define LDK2 40
#define STAGE_BYTES 20480   // A 10240 | B 10240

__device__ __forceinline__ void gemm_prefetch(
    char* smbase, int stage, int row, int hlf,
    const bf16* A, int lda,
    const bf16* B, int ldb,
    int bm, int bn, int M, int k0)
{
    int gra = bm + row;
    int szA = (gra < M) ? 16 : 0;
    if (gra >= M) gra = 0;
    const char* pA = (const char*)(A + (size_t)gra * lda + k0) + hlf * 32;
    int grb = bn + row;
    const char* pB = (const char*)(B + (size_t)grb * ldb + k0) + hlf * 32;
    uint32_t so = (uint32_t)__cvta_generic_to_shared(smbase + stage * STAGE_BYTES)
                  + row * (LDK2 * 2) + hlf * 32;
    cp16(so,         pA,      szA);  cp16(so + 16,         pA + 16, szA);
    cp16(so + 10240, pB,      16);   cp16(so + 10240 + 16, pB + 16, 16);
}

template<int EPI>
__global__ void __launch_bounds__(256)
gemm_bf16(const bf16* __restrict__ A, int lda,
          const bf16* __restrict__ B, int ldb,
          float* __restrict__ C,
          const float* __restrict__ bias,
          bf16* __restrict__ oB, int ostride, int ocoff,
          int M, int K)
{
    extern __shared__ char sm_[];
    int tid = threadIdx.x, wid = tid >> 5, lane = tid & 31;
    int bm = blockIdx.y * 128, bn = blockIdx.x * 128;
    int wm = (wid & 3) * 32, wn = (wid >> 2) * 64;
    int idx = lane >> 3, lr = lane & 7;
    int row = tid >> 1, hlf = tid & 1;

    float acc[2][8][4];
    #pragma unroll
    for (int i = 0; i < 2; i++)
        #pragma unroll
        for (int j = 0; j < 8; j++)
            #pragma unroll
            for (int q = 0; q < 4; q++) acc[i][j][q] = 0.0f;

    int KT = K >> 5;
    gemm_prefetch(sm_, 0, row, hlf, A, lda, B, ldb, bm, bn, M, 0);
    asm volatile("cp.async.commit_group;");

    for (int kt = 0; kt < KT; kt++) {
        int s = kt & 1;
        if (kt + 1 < KT) {
            gemm_prefetch(sm_, s ^ 1, row, hlf, A, lda, B, ldb,
                          bm, bn, M, (kt + 1) << 5);
            asm volatile("cp.async.commit_group;");
            asm volatile("cp.async.wait_group 1;");
        } else {
            asm volatile("cp.async.wait_group 0;");
        }
        __syncthreads();

        const bf16* sA = (const bf16*)(sm_ + s * STAGE_BYTES);
        const bf16* sB = (const bf16*)(sm_ + s * STAGE_BYTES + 10240);

        #pragma unroll
        for (int ks = 0; ks < 2; ks++) {
            int kb = ks * 16;
            uint32_t a[2][4];
            #pragma unroll
            for (int mf = 0; mf < 2; mf++) {
                int rr = wm + mf * 16 + (idx & 1) * 8 + lr;
                int cc2 = kb + (idx >> 1) * 8;
                ldm_x4(a[mf], &sA[rr * LDK2 + cc2]);
            }
            uint32_t b[4][4];
            #pragma unroll
            for (int bg = 0; bg < 4; bg++) {
                int rr = wn + bg * 16 + (idx >> 1) * 8 + lr;
                int cc2 = kb + (idx & 1) * 8;
                ldm_x4(b[bg], &sB[rr * LDK2 + cc2]);
            }
            #pragma unroll
            for (int mf = 0; mf < 2; mf++)
                #pragma unroll
                for (int ng = 0; ng < 8; ng++) {
                    int bg = ng >> 1, pr = (ng & 1) * 2;
                    mma16816(acc[mf][ng], a[mf], b[bg][pr], b[bg][pr + 1]);
                }
        }
        __syncthreads();
    }

    // ---- epilogue ----
    int r0 = bm + wm + (lane >> 2);
    int lc0 = wn + (lane & 3) * 2;
    #pragma unroll
    for (int mf = 0; mf < 2; mf++) {
        #pragma unroll
        for (int hf2 = 0; hf2 < 2; hf2++) {
            int r = r0 + mf * 16 + hf2 * 8;
            if (r >= M) continue;
            #pragma unroll
            for (int ng = 0; ng < 8; ng++) {
                int lc = lc0 + ng * 8;
                int c = bn + lc;
                float v0 = acc[mf][ng][hf2 * 2 + 0];
                float v1 = acc[mf][ng][hf2 * 2 + 1];
                if (EPI == 1) {
                    __half2 t;
                    t.x = __float2half_rn(v0); t.y = __float2half_rn(v1);
                    *(__half2*)((f16*)C + (size_t)r * 512 + c) = t;
                } else if (EPI == 2 || EPI == 3) {
                    v0 += bias[c]; v1 += bias[c + 1];
                    if (EPI == 2) { v0 = fmaxf(v0, 0.f); v1 = fmaxf(v1, 0.f); }
                    __nv_bfloat162 t;
                    t.x = __float2bfloat16(v0); t.y = __float2bfloat16(v1);
                    *(__nv_bfloat162*)(oB + (size_t)r * ostride + ocoff + c) = t;
                } else {
                    v0 += bias[c]; v1 += bias[c + 1];
                    if (EPI == 5) { v0 = fmaxf(v0, 0.f); v1 = fmaxf(v1, 0.f); }
                    float2 st; st.x = v0; st.y = v1;
                    *(float2*)(C + (size_t)r * 256 + c) = st;
                }
            }
        }
    }
}

// ---------------- launch ----------------
#define SMEM_GEMM (2 * STAGE_BYTES)

extern "C" void kernel_launch(void* const* d_in, const int* in_sizes, int n_in,
                              void* d_out, int out_size) {
    const float* x    = (const float*)d_in[0];
    const int*   e1   = (const int*)d_in[1];
    const int*   e2   = (const int*)d_in[2];
    const int*   i1   = (const int*)d_in[3];
    const int*   i2   = (const int*)d_in[4];
    const float* w11  = (const float*)d_in[5];
    const float* b11  = (const float*)d_in[6];
    const float* w12  = (const float*)d_in[7];
    const float* b12  = (const float*)d_in[8];
    const float* w21  = (const float*)d_in[9];
    const float* b21  = (const float*)d_in[10];
    const float* w22  = (const float*)d_in[11];
    const float* b22  = (const float*)d_in[12];
    const float* m1w1 = (const float*)d_in[13];
    const float* m1b1 = (const float*)d_in[14];
    const float* m1w2 = (const float*)d_in[15];
    const float* m1b2 = (const float*)d_in[16];
    const float* m2w1 = (const float*)d_in[17];
    const float* m2b1 = (const float*)d_in[18];
    const float* m2w2 = (const float*)d_in[19];
    const float* m2b2 = (const float*)d_in[20];
    const float* mw1  = (const float*)d_in[21];
    const float* mb1  = (const float*)d_in[22];
    const float* mw2  = (const float*)d_in[23];
    const float* mb2  = (const float*)d_in[24];
    float* out = (float*)d_out;

    int Nn = in_sizes[0] / FIN;
    int E1 = in_sizes[1] / 2;
    int E2 = in_sizes[2] / 2;
    int S  = out_size / CC;

    float* base = nullptr;
    cudaGetSymbolAddress((void**)&base, g_buf);
    f16*  H16   = (f16*)(base + OFF_H);
    float* hf   = base + OFF_HF;
    float* hid2 = base + OFF_HID2;
    float* dis1 = base + OFF_DIS1;
    float* dis2 = base + OFF_DIS2;
    int* cc     = (int*)(base + OFF_CC);
    int* sc     = (int*)(base + OFF_SC);
    int* bsn    = (int*)(base + OFF_BSN);
    int* bss    = (int*)(base + OFF_BSS);
    int* coff   = (int*)(base + OFF_COFF);
    int* ccur   = (int*)(base + OFF_CCUR);
    int* soff   = (int*)(base + OFF_SOFF);
    int* scur   = (int*)(base + OFF_SCUR);
    int* csr    = (int*)(base + OFF_CSR);
    int* slist  = (int*)(base + OFF_SLIST);
    bf16* XB = (bf16*)(base + OFF_XB);
    bf16* YB = (bf16*)(base + OFF_YB);
    bf16* WB = (bf16*)(base + OFF_WB);

    cudaFuncSetAttribute(gemm_bf16<1>, cudaFuncAttributeMaxDynamicSharedMemorySize, SMEM_GEMM);
    cudaFuncSetAttribute(gemm_bf16<2>, cudaFuncAttributeMaxDynamicSharedMemorySize, SMEM_GEMM);
    cudaFuncSetAttribute(gemm_bf16<3>, cudaFuncAttributeMaxDynamicSharedMemorySize, SMEM_GEMM);
    cudaFuncSetAttribute(gemm_bf16<4>, cudaFuncAttributeMaxDynamicSharedMemorySize, SMEM_GEMM);
    cudaFuncSetAttribute(gemm_bf16<5>, cudaFuncAttributeMaxDynamicSharedMemorySize, SMEM_GEMM);

    const int T = 256;
    unsigned gy  = (unsigned)((Nn + 127) / 128);
    unsigned gys = (unsigned)((S + 127) / 128);
    dim3 g512(4, gy), g256(2, gy), gh(2, gys);
    unsigned gGat = (unsigned)((Nn + 3) / 4);
    unsigned gPool = (unsigned)((2 * S + 3) / 4);
    int nbN = (2 * Nn + SCAN_B - 1) / SCAN_B;
    int nbS = (2 * S + SCAN_B - 1) / SCAN_B;
    int nz = (int)(OFF_COFF - OFF_CC);
    long t4;

    // ---- prologue ordered so launch #6 (= ncu -s 5 -c 1 capture) is conv GEMM ----
    t4 = (long)Nn * FIN / 4;
    castA_k<<<(unsigned)((t4 + T - 1) / T), T>>>(x, FIN, XB, 512, 0, t4);               // 1
    castAllW_k<<<(WTOT + T - 1) / T, T>>>(w11, w12, w21, w22, m1w1, m1w2, m2w1, m2w2, mw1, WB); // 2
    zero_k<<<(nz + T - 1) / T, T>>>(base + OFF_CC, nz);                                 // 3
    countall_k<<<(E1 + E2 + Nn + T - 1) / T, T>>>(e1, E1, e2, E2, i1, i2, Nn, S, cc, sc); // 4
    blocksum_k<<<nbN, SCAN_B>>>(cc, bsn, 2 * Nn);                                       // 5
    // ---- layer 1 conv GEMM (launch #6 — profiled) ----
    gemm_bf16<1><<<g512, 256, SMEM_GEMM>>>(XB, 512, WB + WC1, FIN,
        (float*)H16, nullptr, nullptr, 0, 0, Nn, FIN);
    // ---- rest of CSR build ----
    blocksum_k<<<nbS, SCAN_B>>>(sc, bss, 2 * S);
    scanbsum_k<<<1, 32>>>(bsn, nbN, coff + 2 * Nn);
    scanbsum_k<<<1, 32>>>(bss, nbS, soff + 2 * S);
    scanblock_k<<<nbN, SCAN_B>>>(cc, bsn, coff, ccur, 2 * Nn);
    scanblock_k<<<nbS, SCAN_B>>>(sc, bss, soff, scur, 2 * S);
    disint_k<<<(Nn + T - 1) / T, T>>>(cc, dis1, dis2, Nn);
    placeboth_k<<<(E1 + E2 + T - 1) / T, T>>>(e1, E1, e2, E2, Nn, ccur, csr);
    placeseg_k<<<(Nn + T - 1) / T, T>>>(i1, i2, Nn, S, scur, slist);

    // ---- layer 1 gathers ----
    gather_k<<<gGat, T>>>(csr, coff,      dis1, H16,       b11, XB, 0,   Nn);
    gather_k<<<gGat, T>>>(csr, coff + Nn, dis2, H16 + 256, b12, XB, 256, Nn);
    // ---- mlp_1 ----
    gemm_bf16<2><<<g256, 256, SMEM_GEMM>>>(XB, 512, WB + WM1A, 512,
        nullptr, m1b1, YB, 256, 0, Nn, 512);
    gemm_bf16<3><<<g256, 256, SMEM_GEMM>>>(YB, 256, WB + WM1B, 256,
        nullptr, m1b2, XB, 512, 0, Nn, 256);

    // ---- layer 2 ----
    gemm_bf16<1><<<g512, 256, SMEM_GEMM>>>(XB, 512, WB + WC2, DD,
        (float*)H16, nullptr, nullptr, 0, 0, Nn, DD);
    gather_k<<<gGat, T>>>(csr, coff,      dis1, H16,       b21, XB, 0,   Nn);
    gather_k<<<gGat, T>>>(csr, coff + Nn, dis2, H16 + 256, b22, XB, 256, Nn);
    // ---- mlp_2 ----
    gemm_bf16<2><<<g256, 256, SMEM_GEMM>>>(XB, 512, WB + WM2A, 512,
        nullptr, m2b1, YB, 256, 0, Nn, 512);
    gemm_bf16<4><<<g256, 256, SMEM_GEMM>>>(YB, 256, WB + WM2B, 256,
        hf, m2b2, nullptr, 0, 0, Nn, 256);

    // ---- pooling ----
    poolgather_k<<<gPool, T>>>(slist, soff, hf, XB, S);

    // ---- head ----
    gemm_bf16<5><<<gh, 256, SMEM_GEMM>>>(XB, 512, WB + WHD, 512,
        hid2, mb1, nullptr, 0, 0, S, 512);
    final_k<<<S, DD>>>(hid2, mw2, mb2, out);
}

// round 17
// speedup vs baseline: 2.0414x; 1.0259x over previous
#include <cuda_runtime.h>
#include <cuda_bf16.h>
#include <cuda_fp16.h>
#include <math.h>
#include <stdint.h>
#include <cstdint>

// ---------------- Problem constants ----------------
#define DD 256
#define FIN 128
#define CC 7

typedef __nv_bfloat16 bf16;
typedef __half f16;

// ---------------- Scratch layout (float offsets) ----------------
#define OFF_H     0L             // f16 [M,512] conv GEMM out
#define OFF_HF    51200000L      // f16 [M,256] final node features
#define OFF_XB    76800000L      // bf16 [M,512] activations
#define OFF_YB    102400000L     // bf16 [M,256]
#define OFF_WB    153600000L     // bf16 weight arena (720896)
#define OFF_HID2  154400000L
#define OFF_DIS1  155680000L     // dis1[N] ; dis2 contiguous at +N
#define OFF_DIS2  155780000L
// ---- zero block start ----
#define OFF_CC    155880000L     // int[2N]
#define OFF_SC    156080000L     // int[2S]
#define OFF_BSN   156090000L     // int[256]
#define OFF_BSS   156090256L     // int[16]
// ---- zero block end ----
#define OFF_COFF  156090272L     // int[2N+1]
#define OFF_CCUR  156290276L
#define OFF_SOFF  156490276L     // int[2S+1]
#define OFF_SCUR  156500280L
#define OFF_CSR   156510280L     // int[E1+E2]
#define OFF_SLIST 158110280L     // int[2N]
#define SCRATCH_TOTAL 158310280L

// weight arena offsets (bf16 elements)
#define WC1  0
#define WC2  65536
#define WM1A 196608
#define WM1B 327680
#define WM2A 393216
#define WM2B 524288
#define WHD  589824
#define WTOT 720896

__device__ float g_buf[SCRATCH_TOTAL];

// ---------------- helpers ----------------
__device__ __forceinline__ void ldm_x4(uint32_t r[4], const void* p) {
    uint32_t addr = (uint32_t)__cvta_generic_to_shared(p);
    asm volatile("ldmatrix.sync.aligned.m8n8.x4.shared.b16 {%0,%1,%2,%3}, [%4];"
                 : "=r"(r[0]), "=r"(r[1]), "=r"(r[2]), "=r"(r[3]) : "r"(addr));
}

__device__ __forceinline__ void mma16816(float c[4], const uint32_t a[4],
                                         uint32_t b0, uint32_t b1) {
    asm volatile(
        "mma.sync.aligned.m16n8k16.row.col.f32.bf16.bf16.f32 "
        "{%0,%1,%2,%3}, {%4,%5,%6,%7}, {%8,%9}, {%0,%1,%2,%3};"
        : "+f"(c[0]), "+f"(c[1]), "+f"(c[2]), "+f"(c[3])
        : "r"(a[0]), "r"(a[1]), "r"(a[2]), "r"(a[3]), "r"(b0), "r"(b1));
}

__device__ __forceinline__ void cp16(uint32_t s, const void* g, int sz) {
    asm volatile("cp.async.cg.shared.global [%0], [%1], 16, %2;"
                 :: "r"(s), "l"(g), "r"(sz));
}

// ---------------- prologue kernels ----------------
#define SCAN_B 1024

__global__ void zero_k(float* __restrict__ p, int n) {
    int i = blockIdx.x * blockDim.x + threadIdx.x;
    if (i < n) p[i] = 0.0f;
}

__global__ void countall_k(const int* __restrict__ e1, int E1,
                           const int* __restrict__ e2, int E2,
                           const int* __restrict__ i1, const int* __restrict__ i2,
                           int Nn, int S,
                           int* __restrict__ cc, int* __restrict__ sc) {
    int i = blockIdx.x * blockDim.x + threadIdx.x;
    if (i < E1) atomicAdd(&cc[e1[E1 + i]], 1);
    else if (i < E1 + E2) atomicAdd(&cc[Nn + e2[E2 + (i - E1)]], 1);
    else {
        int j = i - E1 - E2;
        if (j < Nn) {
            atomicAdd(&sc[i1[j]], 1);
            atomicAdd(&sc[S + i2[j]], 1);
        }
    }
}

__global__ void blocksum_k(const int* __restrict__ cnt, int* __restrict__ bsum, int n) {
    int i = blockIdx.x * SCAN_B + threadIdx.x;
    int v = (i < n) ? cnt[i] : 0;
    #pragma unroll
    for (int o = 16; o > 0; o >>= 1) v += __shfl_xor_sync(0xFFFFFFFFu, v, o);
    if ((threadIdx.x & 31) == 0) atomicAdd(&bsum[blockIdx.x], v);
}

__global__ void scanbsum_k(int* __restrict__ bsum, int nb, int* __restrict__ off_n) {
    if (threadIdx.x == 0) {
        int acc = 0;
        for (int i = 0; i < nb; i++) { int v = bsum[i]; bsum[i] = acc; acc += v; }
        *off_n = acc;
    }
}

__global__ void scanblock_k(const int* __restrict__ cnt, const int* __restrict__ bsum,
                            int* __restrict__ off, int* __restrict__ cur, int n) {
    __shared__ int sw[32];
    int tid = threadIdx.x, lane = tid & 31, wid = tid >> 5;
    int i = blockIdx.x * SCAN_B + tid;
    int v = (i < n) ? cnt[i] : 0;
    int inc = v;
    #pragma unroll
    for (int o = 1; o < 32; o <<= 1) {
        int t = __shfl_up_sync(0xFFFFFFFFu, inc, o);
        if (lane >= o) inc += t;
    }
    if (lane == 31) sw[wid] = inc;
    __syncthreads();
    if (wid == 0) {
        int t = sw[lane];
        int ti = t;
        #pragma unroll
        for (int o = 1; o < 32; o <<= 1) {
            int u = __shfl_up_sync(0xFFFFFFFFu, ti, o);
            if (lane >= o) ti += u;
        }
        sw[lane] = ti - t;
    }
    __syncthreads();
    int excl = inc - v + sw[wid] + bsum[blockIdx.x];
    if (i < n) { off[i] = excl; cur[i] = excl; }
}

__global__ void disint_k(const int* __restrict__ cc,
                         float* __restrict__ d, int Nn) {
    int i = blockIdx.x * blockDim.x + threadIdx.x;
    if (i < 2 * Nn) d[i] = rsqrtf((float)cc[i] + 1.0f);
}

__global__ void placeboth_k(const int* __restrict__ e1, int E1,
                            const int* __restrict__ e2, int E2, int Nn,
                            int* __restrict__ cur, int* __restrict__ csr) {
    int i = blockIdx.x * blockDim.x + threadIdx.x;
    if (i < E1) {
        int pos = atomicAdd(&cur[e1[E1 + i]], 1);
        csr[pos] = e1[i];
    } else if (i < E1 + E2) {
        int j = i - E1;
        int pos = atomicAdd(&cur[Nn + e2[E2 + j]], 1);
        csr[pos] = e2[j];
    }
}

__global__ void placeseg_k(const int* __restrict__ i1, const int* __restrict__ i2,
                           int Nn, int S,
                           int* __restrict__ scur, int* __restrict__ slist) {
    int i = blockIdx.x * blockDim.x + threadIdx.x;
    if (i < Nn) {
        int p1 = atomicAdd(&scur[i1[i]], 1);
        slist[p1] = i;
        int p2 = atomicAdd(&scur[S + i2[i]], 1);
        slist[p2] = i;
    }
}

// ---------------- merged gather conv (both edge lists, 2N virtual nodes) ----
// g in [0,2N): part = g>=Nn. Reads h fp16 (stride 512, +part*256), writes
// XB[node, part*256 + c] = bf16(relu(bias_part + d^2 h_i + sum coef h_j)).
__global__ void gather_k(const int* __restrict__ csr, const int* __restrict__ coff,
                         const float* __restrict__ disb,   // [2N] concat
                         const f16* __restrict__ h,        // stride 512
                         const float* __restrict__ b1, const float* __restrict__ b2,
                         bf16* __restrict__ oB, int Nn) {
    int g = blockIdx.x * 4 + (threadIdx.x >> 6);
    if (g >= 2 * Nn) return;
    int part = (g >= Nn);
    int node = g - part * Nn;
    int c = (threadIdx.x & 63) << 2;
    const float* bias = part ? b2 : b1;
    const f16* hb = h + part * 256;
    float di = disb[g];
    float d2 = di * di;
    const float* disp = disb + part * Nn;

    const __half2* hp = (const __half2*)(hb + (size_t)node * 512 + c);
    float2 s0 = __half22float2(hp[0]);
    float2 s1 = __half22float2(hp[1]);
    float4 bv = *(const float4*)(bias + c);
    float4 acc;
    acc.x = bv.x + d2 * s0.x; acc.y = bv.y + d2 * s0.y;
    acc.z = bv.z + d2 * s1.x; acc.w = bv.w + d2 * s1.y;

    int s = coff[g], e = coff[g + 1];
    int k = s;
    // 2-way unrolled neighbor loop: two independent row loads in flight
    for (; k + 1 < e; k += 2) {
        int j0 = csr[k], j1 = csr[k + 1];
        float c0 = di * disp[j0];
        float c1 = di * disp[j1];
        const __half2* h0 = (const __half2*)(hb + (size_t)j0 * 512 + c);
        const __half2* h1 = (const __half2*)(hb + (size_t)j1 * 512 + c);
        float2 a0 = __half22float2(h0[0]);
        float2 a1 = __half22float2(h0[1]);
        float2 b0 = __half22float2(h1[0]);
        float2 b1v = __half22float2(h1[1]);
        acc.x += c0 * a0.x + c1 * b0.x;
        acc.y += c0 * a0.y + c1 * b0.y;
        acc.z += c0 * a1.x + c1 * b1v.x;
        acc.w += c0 * a1.y + c1 * b1v.y;
    }
    if (k < e) {
        int j = csr[k];
        float cf = di * disp[j];
        const __half2* hj = (const __half2*)(hb + (size_t)j * 512 + c);
        float2 f0 = __half22float2(hj[0]);
        float2 f1 = __half22float2(hj[1]);
        acc.x += cf * f0.x; acc.y += cf * f0.y;
        acc.z += cf * f1.x; acc.w += cf * f1.y;
    }
    acc.x = fmaxf(acc.x, 0.f); acc.y = fmaxf(acc.y, 0.f);
    acc.z = fmaxf(acc.z, 0.f); acc.w = fmaxf(acc.w, 0.f);
    size_t o = (size_t)node * 512 + part * 256 + c;
    __nv_bfloat162 t0, t1;
    t0.x = __float2bfloat16(acc.x); t0.y = __float2bfloat16(acc.y);
    t1.x = __float2bfloat16(acc.z); t1.y = __float2bfloat16(acc.w);
    *(__nv_bfloat162*)(oB + o) = t0;
    *(__nv_bfloat162*)(oB + o + 2) = t1;
}

// ---------------- pool gather (hf fp16) ----------------
__global__ void poolgather_k(const int* __restrict__ slist, const int* __restrict__ soff,
                             const f16* __restrict__ hf,
                             bf16* __restrict__ oB, int S) {
    int g = blockIdx.x * 4 + (threadIdx.x >> 6);
    if (g >= 2 * S) return;
    int part = (g >= S);
    int seg = g - part * S;
    int c = (threadIdx.x & 63) << 2;
    int s = soff[g], e = soff[g + 1];
    float4 acc = make_float4(0.f, 0.f, 0.f, 0.f);
    int k = s;
    for (; k + 1 < e; k += 2) {
        int n0 = slist[k], n1 = slist[k + 1];
        const __half2* p0 = (const __half2*)(hf + (size_t)n0 * 256 + c);
        const __half2* p1 = (const __half2*)(hf + (size_t)n1 * 256 + c);
        float2 a0 = __half22float2(p0[0]);
        float2 a1 = __half22float2(p0[1]);
        float2 b0 = __half22float2(p1[0]);
        float2 b1 = __half22float2(p1[1]);
        acc.x += a0.x + b0.x; acc.y += a0.y + b0.y;
        acc.z += a1.x + b1.x; acc.w += a1.y + b1.y;
    }
    if (k < e) {
        int n0 = slist[k];
        const __half2* p0 = (const __half2*)(hf + (size_t)n0 * 256 + c);
        float2 a0 = __half22float2(p0[0]);
        float2 a1 = __half22float2(p0[1]);
        acc.x += a0.x; acc.y += a0.y; acc.z += a1.x; acc.w += a1.y;
    }
    float inv = 1.0f / fmaxf((float)(e - s), 1.0f);
    acc.x *= inv; acc.y *= inv; acc.z *= inv; acc.w *= inv;
    size_t o = (size_t)seg * 512 + part * 256 + c;
    __nv_bfloat162 t0, t1;
    t0.x = __float2bfloat16(acc.x); t0.y = __float2bfloat16(acc.y);
    t1.x = __float2bfloat16(acc.z); t1.y = __float2bfloat16(acc.w);
    *(__nv_bfloat162*)(oB + o) = t0;
    *(__nv_bfloat162*)(oB + o + 2) = t1;
}

// ---------------- casts ----------------
__global__ void castA_k(const float* __restrict__ src, int Ks,
                        bf16* __restrict__ dB, int dstride, int coff, long total4) {
    long gid = blockIdx.x * (long)blockDim.x + threadIdx.x;
    if (gid >= total4) return;
    long e = gid * 4;
    long r = e / Ks;
    int  c = (int)(e - r * Ks);
    float4 v = *(const float4*)(src + e);
    __nv_bfloat162 t0, t1;
    t0.x = __float2bfloat16(v.x); t0.y = __float2bfloat16(v.y);
    t1.x = __float2bfloat16(v.z); t1.y = __float2bfloat16(v.w);
    __nv_bfloat162* p = (__nv_bfloat162*)(dB + r * (long)dstride + coff + c);
    p[0] = t0; p[1] = t1;
}

__global__ void castAllW_k(const float* __restrict__ w11, const float* __restrict__ w12,
                           const float* __restrict__ w21, const float* __restrict__ w22,
                           const float* __restrict__ m1w1, const float* __restrict__ m1w2,
                           const float* __restrict__ m2w1, const float* __restrict__ m2w2,
                           const float* __restrict__ mw1,
                           bf16* __restrict__ dB) {
    int gid = blockIdx.x * blockDim.x + threadIdx.x;
    if (gid >= WTOT) return;
    float v; int dst;
    if (gid < 65536) {
        int l = gid, which = l >= 32768, g = l - which * 32768;
        int k = g >> 8, n = g & 255;
        v = which ? w12[g] : w11[g];
        dst = WC1 + (n + which * 256) * 128 + k;
    } else if (gid < 196608) {
        int l = gid - 65536, which = l >= 65536, g = l - which * 65536;
        int k = g >> 8, n = g & 255;
        v = which ? w22[g] : w21[g];
        dst = WC2 + (n + which * 256) * 256 + k;
    } else if (gid < 327680) {
        int g = gid - 196608;
        int k = g >> 8, n = g & 255;
        v = m1w1[g];
        dst = WM1A + n * 512 + k;
    } else if (gid < 393216) {
        int g = gid - 327680;
        int k = g >> 8, n = g & 255;
        v = m1w2[g];
        dst = WM1B + n * 256 + k;
    } else if (gid < 524288) {
        int g = gid - 393216;
        int k = g >> 8, n = g & 255;
        v = m2w1[g];
        dst = WM2A + n * 512 + k;
    } else if (gid < 589824) {
        int g = gid - 524288;
        int k = g >> 8, n = g & 255;
        v = m2w2[g];
        dst = WM2B + n * 256 + k;
    } else {
        int g = gid - 589824;
        int k = g >> 8, n = g & 255;
        v = mw1[g];
        dst = WHD + n * 512 + k;
    }
    dB[dst] = __float2bfloat16(v);
}

// ---------------- head ----------------
__global__ void final_k(const float* __restrict__ hid, const float* __restrict__ w2,
                        const float* __restrict__ b2, float* __restrict__ out) {
    __shared__ float sh[DD];
    __shared__ float lg[CC];
    int s = blockIdx.x;
    int tid = threadIdx.x;
    sh[tid] = hid[(size_t)s * DD + tid];
    __syncthreads();
    int w = tid >> 5, lane = tid & 31;
    if (w < CC) {
        float sum = 0.0f;
        for (int k = lane; k < DD; k += 32) sum += sh[k] * w2[k * CC + w];
        #pragma unroll
        for (int o = 16; o > 0; o >>= 1) sum += __shfl_xor_sync(0xFFFFFFFFu, sum, o);
        if (lane == 0) lg[w] = sum + b2[w];
    }
    __syncthreads();
    if (tid == 0) {
        float mx = -1e30f;
        #pragma unroll
        for (int c = 0; c < CC; c++) mx = fmaxf(mx, lg[c]);
        float se = 0.0f;
        #pragma unroll
        for (int c = 0; c < CC; c++) se += expf(lg[c] - mx);
        float lse = mx + logf(se);
        #pragma unroll
        for (int c = 0; c < CC; c++) out[(size_t)s * CC + c] = lg[c] - lse;
    }
}

// ---------------- plain bf16 double-buffered GEMM ----------------
// EPI=1 RAW_F16 stride512; EPI=2 bf16(relu(acc+b))->oB; EPI=3 bf16(acc+b)->oB;
// EPI=5 f32 relu stride256; EPI=6 f16(acc+b) stride256
#define LDK2 40
#define STAGE_BYTES 20480

__device__ __forceinline__ void gemm_prefetch(
    char* smbase, int stage, int row, int hlf,
    const bf16* A, int lda,
    const bf16* B, int ldb,
    int bm, int bn, int M, int k0)
{
    int gra = bm + row;
    int szA = (gra < M) ? 16 : 0;
    if (gra >= M) gra = 0;
    const char* pA = (const char*)(A + (size_t)gra * lda + k0) + hlf * 32;
    int grb = bn + row;
    const char* pB = (const char*)(B + (size_t)grb * ldb + k0) + hlf * 32;
    uint32_t so = (uint32_t)__cvta_generic_to_shared(smbase + stage * STAGE_BYTES)
                  + row * (LDK2 * 2) + hlf * 32;
    cp16(so,         pA,      szA);  cp16(so + 16,         pA + 16, szA);
    cp16(so + 10240, pB,      16);   cp16(so + 10240 + 16, pB + 16, 16);
}

template<int EPI>
__global__ void __launch_bounds__(256)
gemm_bf16(const bf16* __restrict__ A, int lda,
          const bf16* __restrict__ B, int ldb,
          float* __restrict__ C,
          const float* __restrict__ bias,
          bf16* __restrict__ oB, int ostride, int ocoff,
          int M, int K)
{
    extern __shared__ char sm_[];
    int tid = threadIdx.x, wid = tid >> 5, lane = tid & 31;
    int bm = blockIdx.y * 128, bn = blockIdx.x * 128;
    int wm = (wid & 3) * 32, wn = (wid >> 2) * 64;
    int idx = lane >> 3, lr = lane & 7;
    int row = tid >> 1, hlf = tid & 1;

    float acc[2][8][4];
    #pragma unroll
    for (int i = 0; i < 2; i++)
        #pragma unroll
        for (int j = 0; j < 8; j++)
            #pragma unroll
            for (int q = 0; q < 4; q++) acc[i][j][q] = 0.0f;

    int KT = K >> 5;
    gemm_prefetch(sm_, 0, row, hlf, A, lda, B, ldb, bm, bn, M, 0);
    asm volatile("cp.async.commit_group;");

    for (int kt = 0; kt < KT; kt++) {
        int s = kt & 1;
        if (kt + 1 < KT) {
            gemm_prefetch(sm_, s ^ 1, row, hlf, A, lda, B, ldb,
                          bm, bn, M, (kt + 1) << 5);
            asm volatile("cp.async.commit_group;");
            asm volatile("cp.async.wait_group 1;");
        } else {
            asm volatile("cp.async.wait_group 0;");
        }
        __syncthreads();

        const bf16* sA = (const bf16*)(sm_ + s * STAGE_BYTES);
        const bf16* sB = (const bf16*)(sm_ + s * STAGE_BYTES + 10240);

        #pragma unroll
        for (int ks = 0; ks < 2; ks++) {
            int kb = ks * 16;
            uint32_t a[2][4];
            #pragma unroll
            for (int mf = 0; mf < 2; mf++) {
                int rr = wm + mf * 16 + (idx & 1) * 8 + lr;
                int cc2 = kb + (idx >> 1) * 8;
                ldm_x4(a[mf], &sA[rr * LDK2 + cc2]);
            }
            uint32_t b[4][4];
            #pragma unroll
            for (int bg = 0; bg < 4; bg++) {
                int rr = wn + bg * 16 + (idx >> 1) * 8 + lr;
                int cc2 = kb + (idx & 1) * 8;
                ldm_x4(b[bg], &sB[rr * LDK2 + cc2]);
            }
            #pragma unroll
            for (int mf = 0; mf < 2; mf++)
                #pragma unroll
                for (int ng = 0; ng < 8; ng++) {
                    int bg = ng >> 1, pr = (ng & 1) * 2;
                    mma16816(acc[mf][ng], a[mf], b[bg][pr], b[bg][pr + 1]);
                }
        }
        __syncthreads();
    }

    // ---- epilogue ----
    int r0 = bm + wm + (lane >> 2);
    int lc0 = wn + (lane & 3) * 2;
    #pragma unroll
    for (int mf = 0; mf < 2; mf++) {
        #pragma unroll
        for (int hf2 = 0; hf2 < 2; hf2++) {
            int r = r0 + mf * 16 + hf2 * 8;
            if (r >= M) continue;
            #pragma unroll
            for (int ng = 0; ng < 8; ng++) {
                int lc = lc0 + ng * 8;
                int c = bn + lc;
                float v0 = acc[mf][ng][hf2 * 2 + 0];
                float v1 = acc[mf][ng][hf2 * 2 + 1];
                if (EPI == 1) {
                    __half2 t;
                    t.x = __float2half_rn(v0); t.y = __float2half_rn(v1);
                    *(__half2*)((f16*)C + (size_t)r * 512 + c) = t;
                } else if (EPI == 2 || EPI == 3) {
                    v0 += bias[c]; v1 += bias[c + 1];
                    if (EPI == 2) { v0 = fmaxf(v0, 0.f); v1 = fmaxf(v1, 0.f); }
                    __nv_bfloat162 t;
                    t.x = __float2bfloat16(v0); t.y = __float2bfloat16(v1);
                    *(__nv_bfloat162*)(oB + (size_t)r * ostride + ocoff + c) = t;
                } else if (EPI == 6) {
                    v0 += bias[c]; v1 += bias[c + 1];
                    __half2 t;
                    t.x = __float2half_rn(v0); t.y = __float2half_rn(v1);
                    *(__half2*)((f16*)C + (size_t)r * 256 + c) = t;
                } else {
                    v0 += bias[c]; v1 += bias[c + 1];
                    if (EPI == 5) { v0 = fmaxf(v0, 0.f); v1 = fmaxf(v1, 0.f); }
                    float2 st; st.x = v0; st.y = v1;
                    *(float2*)(C + (size_t)r * 256 + c) = st;
                }
            }
        }
    }
}

// ---------------- launch ----------------
#define SMEM_GEMM (2 * STAGE_BYTES)

extern "C" void kernel_launch(void* const* d_in, const int* in_sizes, int n_in,
                              void* d_out, int out_size) {
    const float* x    = (const float*)d_in[0];
    const int*   e1   = (const int*)d_in[1];
    const int*   e2   = (const int*)d_in[2];
    const int*   i1   = (const int*)d_in[3];
    const int*   i2   = (const int*)d_in[4];
    const float* w11  = (const float*)d_in[5];
    const float* b11  = (const float*)d_in[6];
    const float* w12  = (const float*)d_in[7];
    const float* b12  = (const float*)d_in[8];
    const float* w21  = (const float*)d_in[9];
    const float* b21  = (const float*)d_in[10];
    const float* w22  = (const float*)d_in[11];
    const float* b22  = (const float*)d_in[12];
    const float* m1w1 = (const float*)d_in[13];
    const float* m1b1 = (const float*)d_in[14];
    const float* m1w2 = (const float*)d_in[15];
    const float* m1b2 = (const float*)d_in[16];
    const float* m2w1 = (const float*)d_in[17];
    const float* m2b1 = (const float*)d_in[18];
    const float* m2w2 = (const float*)d_in[19];
    const float* m2b2 = (const float*)d_in[20];
    const float* mw1  = (const float*)d_in[21];
    const float* mb1  = (const float*)d_in[22];
    const float* mw2  = (const float*)d_in[23];
    const float* mb2  = (const float*)d_in[24];
    float* out = (float*)d_out;

    int Nn = in_sizes[0] / FIN;
    int E1 = in_sizes[1] / 2;
    int E2 = in_sizes[2] / 2;
    int S  = out_size / CC;

    float* base = nullptr;
    cudaGetSymbolAddress((void**)&base, g_buf);
    f16*  H16   = (f16*)(base + OFF_H);
    f16*  HF16  = (f16*)(base + OFF_HF);
    float* hid2 = base + OFF_HID2;
    float* disb = base + OFF_DIS1;     // [2N] contiguous
    int* cc     = (int*)(base + OFF_CC);
    int* sc     = (int*)(base + OFF_SC);
    int* bsn    = (int*)(base + OFF_BSN);
    int* bss    = (int*)(base + OFF_BSS);
    int* coff   = (int*)(base + OFF_COFF);
    int* ccur   = (int*)(base + OFF_CCUR);
    int* soff   = (int*)(base + OFF_SOFF);
    int* scur   = (int*)(base + OFF_SCUR);
    int* csr    = (int*)(base + OFF_CSR);
    int* slist  = (int*)(base + OFF_SLIST);
    bf16* XB = (bf16*)(base + OFF_XB);
    bf16* YB = (bf16*)(base + OFF_YB);
    bf16* WB = (bf16*)(base + OFF_WB);

    cudaFuncSetAttribute(gemm_bf16<1>, cudaFuncAttributeMaxDynamicSharedMemorySize, SMEM_GEMM);
    cudaFuncSetAttribute(gemm_bf16<2>, cudaFuncAttributeMaxDynamicSharedMemorySize, SMEM_GEMM);
    cudaFuncSetAttribute(gemm_bf16<3>, cudaFuncAttributeMaxDynamicSharedMemorySize, SMEM_GEMM);
    cudaFuncSetAttribute(gemm_bf16<5>, cudaFuncAttributeMaxDynamicSharedMemorySize, SMEM_GEMM);
    cudaFuncSetAttribute(gemm_bf16<6>, cudaFuncAttributeMaxDynamicSharedMemorySize, SMEM_GEMM);

    const int T = 256;
    unsigned gy  = (unsigned)((Nn + 127) / 128);
    unsigned gys = (unsigned)((S + 127) / 128);
    dim3 g512(4, gy), g256(2, gy), gh(2, gys);
    unsigned gGat = (unsigned)((2 * Nn + 3) / 4);
    unsigned gPool = (unsigned)((2 * S + 3) / 4);
    int nbN = (2 * Nn + SCAN_B - 1) / SCAN_B;
    int nbS = (2 * S + SCAN_B - 1) / SCAN_B;
    int nz = (int)(OFF_COFF - OFF_CC);
    long t4;

    // ---- prologue ----
    t4 = (long)Nn * FIN / 4;
    castA_k<<<(unsigned)((t4 + T - 1) / T), T>>>(x, FIN, XB, 512, 0, t4);
    castAllW_k<<<(WTOT + T - 1) / T, T>>>(w11, w12, w21, w22, m1w1, m1w2, m2w1, m2w2, mw1, WB);
    zero_k<<<(nz + T - 1) / T, T>>>(base + OFF_CC, nz);
    countall_k<<<(E1 + E2 + Nn + T - 1) / T, T>>>(e1, E1, e2, E2, i1, i2, Nn, S, cc, sc);
    blocksum_k<<<nbN, SCAN_B>>>(cc, bsn, 2 * Nn);
    // ---- layer 1 conv GEMM ----
    gemm_bf16<1><<<g512, 256, SMEM_GEMM>>>(XB, 512, WB + WC1, FIN,
        (float*)H16, nullptr, nullptr, 0, 0, Nn, FIN);
    // ---- rest of CSR build ----
    blocksum_k<<<nbS, SCAN_B>>>(sc, bss, 2 * S);
    scanbsum_k<<<1, 32>>>(bsn, nbN, coff + 2 * Nn);
    scanbsum_k<<<1, 32>>>(bss, nbS, soff + 2 * S);
    scanblock_k<<<nbN, SCAN_B>>>(cc, bsn, coff, ccur, 2 * Nn);
    scanblock_k<<<nbS, SCAN_B>>>(sc, bss, soff, scur, 2 * S);
    disint_k<<<(2 * Nn + T - 1) / T, T>>>(cc, disb, Nn);
    placeboth_k<<<(E1 + E2 + T - 1) / T, T>>>(e1, E1, e2, E2, Nn, ccur, csr);
    placeseg_k<<<(Nn + T - 1) / T, T>>>(i1, i2, Nn, S, scur, slist);

    // ---- layer 1 gather (merged, both lists) ----
    gather_k<<<gGat, T>>>(csr, coff, disb, H16, b11, b12, XB, Nn);
    // ---- mlp_1 ----
    gemm_bf16<2><<<g256, 256, SMEM_GEMM>>>(XB, 512, WB + WM1A, 512,
        nullptr, m1b1, YB, 256, 0, Nn, 512);
    gemm_bf16<3><<<g256, 256, SMEM_GEMM>>>(YB, 256, WB + WM1B, 256,
        nullptr, m1b2, XB, 512, 0, Nn, 256);

    // ---- layer 2 ----
    gemm_bf16<1><<<g512, 256, SMEM_GEMM>>>(XB, 512, WB + WC2, DD,
        (float*)H16, nullptr, nullptr, 0, 0, Nn, DD);
    gather_k<<<gGat, T>>>(csr, coff, disb, H16, b21, b22, XB, Nn);
    // ---- mlp_2 ----
    gemm_bf16<2><<<g256, 256, SMEM_GEMM>>>(XB, 512, WB + WM2A, 512,
        nullptr, m2b1, YB, 256, 0, Nn, 512);
    gemm_bf16<6><<<g256, 256, SMEM_GEMM>>>(YB, 256, WB + WM2B, 256,
        (float*)HF16, m2b2, nullptr, 0, 0, Nn, 256);

    // ---- pooling ----
    poolgather_k<<<gPool, T>>>(slist, soff, HF16, XB, S);

    // ---- head ----
    gemm_bf16<5><<<gh, 256, SMEM_GEMM>>>(XB, 512, WB + WHD, 512,
        hid2, mb1, nullptr, 0, 0, S, 512);
    final_k<<<S, DD>>>(hid2, mw2, mb2, out);
}